// round 8
// baseline (speedup 1.0000x reference)
#include <cuda_runtime.h>
#include <cuda_bf16.h>
#include <math.h>

#define B_  2
#define T_  3
#define N_  6
#define C_  16
#define FD_ 48
#define FH_ 24
#define FW_ 64
#define GX_ 100
#define GY_ 100
#define GZ_ 8
#define OC_ 40

#define VOXN (GX_*GZ_*GY_)          // 80000 spatial positions per (b,t)
#define FEAT_PER_CAM (FD_*FH_*FW_*C_)

// Scratch (static device allocations — no cudaMalloc allowed)
__device__ float g_featCL[(size_t)B_*T_*N_*FD_*FH_*FW_*C_]; // 42,467,328 floats (~170MB), channel-last
__device__ float g_h[(size_t)B_*T_*VOXN*OC_];               // 19,200,000 floats (~77MB), channel-last
__device__ float g_cum[B_*T_*12];                           // top-3 rows of cumulative warp matrices

// ---------------------------------------------------------------------------
// Kernel 0: transpose frustum features [m][c][fd][fh][fw] -> [m][fd][fh][fw][c]
// One block per (m, fd, fh) row; tile in smem with padding for conflict-free access.
// ---------------------------------------------------------------------------
__global__ void k_transpose(const float* __restrict__ in) {
    __shared__ float tile[FW_*17];   // [fw][c], pad 17 to kill bank conflicts
    int r  = blockIdx.x;                 // over B*T*N*FD*FH
    int m  = r / (FD_*FH_);
    int dh = r % (FD_*FH_);
    for (int idx = threadIdx.x; idx < C_*FW_; idx += blockDim.x) {
        int c  = idx / FW_;
        int fw = idx % FW_;
        tile[fw*17 + c] = in[(((size_t)m*C_ + c)*(FD_*FH_) + dh)*FW_ + fw];
    }
    __syncthreads();
    float* dst = g_featCL + (size_t)r * (FW_*C_);
    for (int idx = threadIdx.x; idx < C_*FW_; idx += blockDim.x) {
        int fw = idx / C_;
        int c  = idx % C_;
        dst[idx] = tile[fw*17 + c];
    }
}

// ---------------------------------------------------------------------------
// Kernel: cumulative warp matrices.  cum_{T-1}=I; cum_t = M4[t] @ cum_{t+1}
// where M4 = [DoF rows 0..2 ; 0 0 0 1].  Store top 3 rows per (b,t).
// ---------------------------------------------------------------------------
__global__ void k_cum(const float* __restrict__ DoF) {
    int b = threadIdx.x;
    if (b >= B_) return;
    float cum[16] = {1,0,0,0, 0,1,0,0, 0,0,1,0, 0,0,0,1};
    for (int t = T_-1; t >= 0; --t) {
        if (t < T_-1) {
            float M[16];
            #pragma unroll
            for (int i = 0; i < 3; i++)
                #pragma unroll
                for (int j = 0; j < 4; j++)
                    M[i*4+j] = DoF[((b*T_ + t)*4 + i)*4 + j];
            M[12]=0.f; M[13]=0.f; M[14]=0.f; M[15]=1.f;
            float nc[16];
            #pragma unroll
            for (int i = 0; i < 4; i++)
                #pragma unroll
                for (int j = 0; j < 4; j++) {
                    float a = 0.f;
                    #pragma unroll
                    for (int k = 0; k < 4; k++) a += M[i*4+k]*cum[k*4+j];
                    nc[i*4+j] = a;
                }
            #pragma unroll
            for (int i = 0; i < 16; i++) cum[i] = nc[i];
        }
        for (int i = 0; i < 12; i++) g_cum[(b*T_+t)*12 + i] = cum[i];
    }
}

// ---------------------------------------------------------------------------
// Kernel 1: for each voxel (b,t,x,gz,gy): project into 6 cameras, trilinear-
// sample 16 channels each, apply W_N (96->40) + bias + ReLU, store channel-last h.
// ---------------------------------------------------------------------------
__global__ void __launch_bounds__(128) k_frustum(
    const float* __restrict__ RT, const float* __restrict__ intr,
    const float* __restrict__ W_N, const float* __restrict__ b_N)
{
    __shared__ float sP[N_*12];          // fused K @ RT[:3,:] per camera
    __shared__ float sW[OC_*N_*C_];      // 3840
    __shared__ float sb[OC_];

    int pos = blockIdx.x*128 + threadIdx.x;     // 480000 total, VOXN % 128 == 0
    int bt  = pos / VOXN;                       // block-uniform
    int t   = bt % T_;
    int b   = bt / T_;
    int rem = pos % VOXN;
    int gy  = rem % GY_;
    int gz  = (rem / GY_) % GZ_;
    int x   = rem / (GY_*GZ_);

    for (int i = threadIdx.x; i < OC_*N_*C_; i += 128) sW[i] = W_N[i];
    if (threadIdx.x < OC_) sb[threadIdx.x] = b_N[threadIdx.x];
    if (threadIdx.x < N_) {
        const float* K = intr + b*9;
        const float* R = RT + ((size_t)((b*T_+t)*N_ + threadIdx.x))*16;
        #pragma unroll
        for (int i = 0; i < 3; i++)
            #pragma unroll
            for (int j = 0; j < 4; j++)
                sP[threadIdx.x*12 + i*4 + j] =
                    K[i*3+0]*R[0*4+j] + K[i*3+1]*R[1*4+j] + K[i*3+2]*R[2*4+j];
    }
    __syncthreads();

    // Voxel center (vs = 1,1,1 given the shapes)
    float px = -50.0f + ((float)x  + 0.5f);
    float py = -50.0f + ((float)gy + 0.5f);
    float pz = -3.0f  + ((float)gz + 0.5f);

    float acc[OC_];
    #pragma unroll
    for (int o = 0; o < OC_; o++) acc[o] = sb[o];

    for (int n = 0; n < N_; n++) {
        const float* P = sP + n*12;
        float pr0 = P[0]*px + P[1]*py + P[2]*pz  + P[3];
        float pr1 = P[4]*px + P[5]*py + P[6]*pz  + P[7];
        float pr2 = P[8]*px + P[9]*py + P[10]*pz + P[11];
        float zc = fmaxf(pr2, 1e-5f);
        float u = pr0 / zc;
        float v = pr1 / zc;
        float d = (pr2 - 2.0f) / ((46.8f - 2.0f) / 48.0f);
        // clamp to avoid int-conversion UB; preserves out-of-range invalidity
        u = fminf(fmaxf(u, -1.0e6f), 1.0e6f);
        v = fminf(fmaxf(v, -1.0e6f), 1.0e6f);
        d = fminf(fmaxf(d, -1.0e6f), 1.0e6f);

        float fx0 = floorf(u), fy0 = floorf(v), fz0 = floorf(d);
        int x0 = (int)fx0, y0 = (int)fy0, z0 = (int)fz0;
        float wx1 = u - fx0, wy1 = v - fy0, wz1 = d - fz0;

        float s[C_];
        #pragma unroll
        for (int c = 0; c < C_; c++) s[c] = 0.f;

        const float* fb = g_featCL + (size_t)((b*T_+t)*N_ + n)*FEAT_PER_CAM;
        #pragma unroll
        for (int dz = 0; dz < 2; dz++) {
            int zi = z0 + dz;
            if (zi < 0 || zi >= FD_) continue;
            float wz = dz ? wz1 : (1.0f - wz1);
            #pragma unroll
            for (int dy = 0; dy < 2; dy++) {
                int yi = y0 + dy;
                if (yi < 0 || yi >= FH_) continue;
                float wzy = wz * (dy ? wy1 : (1.0f - wy1));
                #pragma unroll
                for (int dx = 0; dx < 2; dx++) {
                    int xi = x0 + dx;
                    if (xi < 0 || xi >= FW_) continue;
                    float w = wzy * (dx ? wx1 : (1.0f - wx1));
                    const float4* p = reinterpret_cast<const float4*>(
                        fb + (size_t)((zi*FH_ + yi)*FW_ + xi)*C_);
                    float4 a0 = p[0], a1 = p[1], a2 = p[2], a3 = p[3];
                    s[0]+=w*a0.x;  s[1]+=w*a0.y;  s[2]+=w*a0.z;  s[3]+=w*a0.w;
                    s[4]+=w*a1.x;  s[5]+=w*a1.y;  s[6]+=w*a1.z;  s[7]+=w*a1.w;
                    s[8]+=w*a2.x;  s[9]+=w*a2.y;  s[10]+=w*a2.z; s[11]+=w*a2.w;
                    s[12]+=w*a3.x; s[13]+=w*a3.y; s[14]+=w*a3.z; s[15]+=w*a3.w;
                }
            }
        }
        const float* wrow = sW + n*C_;
        #pragma unroll
        for (int o = 0; o < OC_; o++) {
            float a = 0.f;
            #pragma unroll
            for (int c = 0; c < C_; c++) a += wrow[o*(N_*C_) + c] * s[c];
            acc[o] += a;
        }
    }

    float* hout = g_h + (size_t)pos * OC_;
    #pragma unroll
    for (int o = 0; o < OC_; o++) hout[o] = fmaxf(acc[o], 0.0f);
}

// ---------------------------------------------------------------------------
// Kernel 2: for each (b,dd,hh,wy): for each t, warp via cum matrix, trilinear-
// sample 40 channels of h, apply W_T (120->40) + bias + ReLU, write output.
// ---------------------------------------------------------------------------
__global__ void __launch_bounds__(128) k_warp(
    const float* __restrict__ W_T, const float* __restrict__ b_T,
    float* __restrict__ out)
{
    __shared__ float sW[OC_*T_*OC_];   // 4800
    __shared__ float sb[OC_];
    __shared__ float sC[T_*12];

    int pos = blockIdx.x*128 + threadIdx.x;     // 160000 total
    int b   = pos / VOXN;                       // block-uniform
    int rem = pos % VOXN;
    int wy  = rem % GY_;                        // Wp index
    int hh  = (rem / GY_) % GZ_;                // Hp index
    int dd  = rem / (GY_*GZ_);                  // Dp index

    for (int i = threadIdx.x; i < OC_*T_*OC_; i += 128) sW[i] = W_T[i];
    if (threadIdx.x < OC_)    sb[threadIdx.x] = b_T[threadIdx.x];
    if (threadIdx.x < T_*12)  sC[threadIdx.x] = g_cum[b*T_*12 + threadIdx.x];
    __syncthreads();

    float bx = -1.0f + 2.0f*(float)wy / (float)(GY_-1);
    float by = -1.0f + 2.0f*(float)hh / (float)(GZ_-1);
    float bz = -1.0f + 2.0f*(float)dd / (float)(GX_-1);

    float acc[OC_];
    #pragma unroll
    for (int o = 0; o < OC_; o++) acc[o] = sb[o];

    for (int t = 0; t < T_; t++) {
        const float* th = sC + t*12;
        float gx = th[0]*bx + th[1]*by + th[2]*bz  + th[3];
        float gy = th[4]*bx + th[5]*by + th[6]*bz  + th[7];
        float gz = th[8]*bx + th[9]*by + th[10]*bz + th[11];
        float ix = (gx + 1.0f)*0.5f*(float)(GY_-1);   // Wp
        float iy = (gy + 1.0f)*0.5f*(float)(GZ_-1);   // Hp
        float iz = (gz + 1.0f)*0.5f*(float)(GX_-1);   // Dp
        ix = fminf(fmaxf(ix, -1.0e6f), 1.0e6f);
        iy = fminf(fmaxf(iy, -1.0e6f), 1.0e6f);
        iz = fminf(fmaxf(iz, -1.0e6f), 1.0e6f);

        float fx0 = floorf(ix), fy0 = floorf(iy), fz0 = floorf(iz);
        int x0 = (int)fx0, y0 = (int)fy0, z0 = (int)fz0;
        float wx1 = ix - fx0, wy1 = iy - fy0, wz1 = iz - fz0;

        float wv[OC_];
        #pragma unroll
        for (int o = 0; o < OC_; o++) wv[o] = 0.f;

        const float* hb = g_h + (size_t)(b*T_+t)*VOXN*OC_;
        #pragma unroll
        for (int dz = 0; dz < 2; dz++) {
            int zi = z0 + dz;                       // Dp index
            if (zi < 0 || zi >= GX_) continue;
            float wz = dz ? wz1 : (1.0f - wz1);
            #pragma unroll
            for (int dy = 0; dy < 2; dy++) {
                int yi = y0 + dy;                   // Hp index
                if (yi < 0 || yi >= GZ_) continue;
                float wzy = wz * (dy ? wy1 : (1.0f - wy1));
                #pragma unroll
                for (int dx = 0; dx < 2; dx++) {
                    int xi = x0 + dx;               // Wp index
                    if (xi < 0 || xi >= GY_) continue;
                    float w = wzy * (dx ? wx1 : (1.0f - wx1));
                    const float4* p = reinterpret_cast<const float4*>(
                        hb + (size_t)(((zi*GZ_ + yi)*GY_) + xi)*OC_);
                    #pragma unroll
                    for (int q = 0; q < OC_/4; q++) {
                        float4 vq = p[q];
                        wv[q*4+0] += w*vq.x;
                        wv[q*4+1] += w*vq.y;
                        wv[q*4+2] += w*vq.z;
                        wv[q*4+3] += w*vq.w;
                    }
                }
            }
        }
        const float* wrow = sW + t*OC_;
        #pragma unroll
        for (int o = 0; o < OC_; o++) {
            float a = 0.f;
            #pragma unroll
            for (int oc = 0; oc < OC_; oc++) a += wrow[o*(T_*OC_) + oc] * wv[oc];
            acc[o] += a;
        }
    }

    // out[b][o][dd][hh][wy]
    #pragma unroll
    for (int o = 0; o < OC_; o++) {
        out[(((size_t)(b*OC_+o)*GX_ + dd)*GZ_ + hh)*GY_ + wy] = fmaxf(acc[o], 0.0f);
    }
}

// ---------------------------------------------------------------------------
extern "C" void kernel_launch(void* const* d_in, const int* in_sizes, int n_in,
                              void* d_out, int out_size) {
    const float* frustum = (const float*)d_in[0];
    const float* RT      = (const float*)d_in[1];
    const float* intrins = (const float*)d_in[2];
    const float* DoF     = (const float*)d_in[3];
    const float* W_N     = (const float*)d_in[4];
    const float* b_N     = (const float*)d_in[5];
    const float* W_T     = (const float*)d_in[6];
    const float* b_T     = (const float*)d_in[7];
    float* out = (float*)d_out;

    k_transpose<<<B_*T_*N_*FD_*FH_, 256>>>(frustum);
    k_cum<<<1, 32>>>(DoF);
    k_frustum<<<(B_*T_*VOXN)/128, 128>>>(RT, intrins, W_N, b_N);
    k_warp<<<(B_*VOXN)/128, 128>>>(W_T, b_T, out);
}

// round 9
// speedup vs baseline: 1.1267x; 1.1267x over previous
#include <cuda_runtime.h>
#include <cuda_bf16.h>
#include <cuda_fp16.h>
#include <math.h>

#define B_  2
#define T_  3
#define N_  6
#define C_  16
#define FD_ 48
#define FH_ 24
#define FW_ 64
#define GX_ 100
#define GY_ 100
#define GZ_ 8
#define OC_ 40

#define VOXN (GX_*GZ_*GY_)          // 80000 spatial positions per (b,t)
#define FEAT_PER_CAM (FD_*FH_*FW_*C_)

// Scratch (static device allocations — no cudaMalloc allowed)
__device__ __half g_featCL[(size_t)B_*T_*N_*FD_*FH_*FW_*C_]; // channel-last fp16 (~85MB)
__device__ float  g_h[(size_t)B_*T_*VOXN*OC_];               // W_T-premultiplied h', channel-last (~77MB)
__device__ float  g_cum[B_*T_*12];                           // top-3 rows of cumulative warp matrices

// ---------------------------------------------------------------------------
// Kernel 0: transpose frustum features [m][c][fd][fh][fw] -> [m][fd][fh][fw][c]
// fp32 in, fp16 out. One block per (m, fd, fh) row.
// ---------------------------------------------------------------------------
__global__ void k_transpose(const float* __restrict__ in) {
    __shared__ float tile[FW_*17];   // [fw][c], pad to kill bank conflicts
    int r  = blockIdx.x;                 // over B*T*N*FD*FH
    int m  = r / (FD_*FH_);
    int dh = r % (FD_*FH_);
    for (int idx = threadIdx.x; idx < C_*FW_; idx += blockDim.x) {
        int c  = idx / FW_;
        int fw = idx % FW_;
        tile[fw*17 + c] = in[(((size_t)m*C_ + c)*(FD_*FH_) + dh)*FW_ + fw];
    }
    __syncthreads();
    __half2* dst = reinterpret_cast<__half2*>(g_featCL + (size_t)r * (FW_*C_));
    for (int j = threadIdx.x; j < C_*FW_/2; j += blockDim.x) {
        int fw = j / (C_/2);
        int c  = (j % (C_/2)) * 2;
        dst[j] = __floats2half2_rn(tile[fw*17 + c], tile[fw*17 + c + 1]);
    }
}

// ---------------------------------------------------------------------------
// Cumulative warp matrices.  cum_{T-1}=I; cum_t = M4[t] @ cum_{t+1}
// ---------------------------------------------------------------------------
__global__ void k_cum(const float* __restrict__ DoF) {
    int b = threadIdx.x;
    if (b >= B_) return;
    float cum[16] = {1,0,0,0, 0,1,0,0, 0,0,1,0, 0,0,0,1};
    for (int t = T_-1; t >= 0; --t) {
        if (t < T_-1) {
            float M[16];
            #pragma unroll
            for (int i = 0; i < 3; i++)
                #pragma unroll
                for (int j = 0; j < 4; j++)
                    M[i*4+j] = DoF[((b*T_ + t)*4 + i)*4 + j];
            M[12]=0.f; M[13]=0.f; M[14]=0.f; M[15]=1.f;
            float nc[16];
            #pragma unroll
            for (int i = 0; i < 4; i++)
                #pragma unroll
                for (int j = 0; j < 4; j++) {
                    float a = 0.f;
                    #pragma unroll
                    for (int k = 0; k < 4; k++) a += M[i*4+k]*cum[k*4+j];
                    nc[i*4+j] = a;
                }
            #pragma unroll
            for (int i = 0; i < 16; i++) cum[i] = nc[i];
        }
        for (int i = 0; i < 12; i++) g_cum[(b*T_+t)*12 + i] = cum[i];
    }
}

// ---------------------------------------------------------------------------
// Kernel 1: per voxel (b,t,x,gz,gy): project into 6 cams, trilinear-sample 16
// fp16 channels each, W_N (96->40) + b_N + ReLU, then premultiply by the
// per-t slice of W_T (40x40) and store h' channel-last.
// ---------------------------------------------------------------------------
__global__ void __launch_bounds__(128) k_frustum(
    const float* __restrict__ RT, const float* __restrict__ intr,
    const float* __restrict__ W_N, const float* __restrict__ b_N,
    const float* __restrict__ W_T)
{
    __shared__ float sP[N_*12];          // fused K @ RT[:3,:] per camera
    __shared__ float sW[OC_*N_*C_];      // 3840
    __shared__ float sb[OC_];
    __shared__ float sWT[OC_*OC_];       // per-t slice of W_T (1600)

    int pos = blockIdx.x*128 + threadIdx.x;     // 480000 total; VOXN%128==0
    int bt  = pos / VOXN;                       // block-uniform
    int t   = bt % T_;
    int b   = bt / T_;
    int rem = pos % VOXN;
    int gy  = rem % GY_;
    int gz  = (rem / GY_) % GZ_;
    int x   = rem / (GY_*GZ_);

    for (int i = threadIdx.x; i < OC_*N_*C_; i += 128) sW[i] = W_N[i];
    for (int i = threadIdx.x; i < OC_*OC_; i += 128) {
        int o = i / OC_, oc = i % OC_;
        sWT[i] = W_T[o*(T_*OC_) + t*OC_ + oc];
    }
    if (threadIdx.x < OC_) sb[threadIdx.x] = b_N[threadIdx.x];
    if (threadIdx.x < N_) {
        const float* K = intr + b*9;
        const float* R = RT + ((size_t)((b*T_+t)*N_ + threadIdx.x))*16;
        #pragma unroll
        for (int i = 0; i < 3; i++)
            #pragma unroll
            for (int j = 0; j < 4; j++)
                sP[threadIdx.x*12 + i*4 + j] =
                    K[i*3+0]*R[0*4+j] + K[i*3+1]*R[1*4+j] + K[i*3+2]*R[2*4+j];
    }
    __syncthreads();

    float px = -50.0f + ((float)x  + 0.5f);
    float py = -50.0f + ((float)gy + 0.5f);
    float pz = -3.0f  + ((float)gz + 0.5f);

    float acc[OC_];
    #pragma unroll
    for (int o = 0; o < OC_; o++) acc[o] = sb[o];

    for (int n = 0; n < N_; n++) {
        const float* P = sP + n*12;
        float pr0 = P[0]*px + P[1]*py + P[2]*pz  + P[3];
        float pr1 = P[4]*px + P[5]*py + P[6]*pz  + P[7];
        float pr2 = P[8]*px + P[9]*py + P[10]*pz + P[11];
        float zc = fmaxf(pr2, 1e-5f);
        float u = pr0 / zc;
        float v = pr1 / zc;
        float d = (pr2 - 2.0f) / ((46.8f - 2.0f) / 48.0f);
        u = fminf(fmaxf(u, -1.0e6f), 1.0e6f);
        v = fminf(fmaxf(v, -1.0e6f), 1.0e6f);
        d = fminf(fmaxf(d, -1.0e6f), 1.0e6f);

        float fx0 = floorf(u), fy0 = floorf(v), fz0 = floorf(d);
        int x0 = (int)fx0, y0 = (int)fy0, z0 = (int)fz0;
        float wx1 = u - fx0, wy1 = v - fy0, wz1 = d - fz0;

        float s[C_];
        #pragma unroll
        for (int c = 0; c < C_; c++) s[c] = 0.f;

        const __half* fb = g_featCL + (size_t)((b*T_+t)*N_ + n)*FEAT_PER_CAM;
        #pragma unroll
        for (int dz = 0; dz < 2; dz++) {
            int zi = z0 + dz;
            if (zi < 0 || zi >= FD_) continue;
            float wz = dz ? wz1 : (1.0f - wz1);
            #pragma unroll
            for (int dy = 0; dy < 2; dy++) {
                int yi = y0 + dy;
                if (yi < 0 || yi >= FH_) continue;
                float wzy = wz * (dy ? wy1 : (1.0f - wy1));
                #pragma unroll
                for (int dx = 0; dx < 2; dx++) {
                    int xi = x0 + dx;
                    if (xi < 0 || xi >= FW_) continue;
                    float w = wzy * (dx ? wx1 : (1.0f - wx1));
                    union { uint4 u4; __half2 h[8]; } U0, U1;
                    const uint4* p = reinterpret_cast<const uint4*>(
                        fb + (size_t)((zi*FH_ + yi)*FW_ + xi)*C_);
                    U0.u4 = p[0]; U1.u4 = p[1];
                    #pragma unroll
                    for (int q = 0; q < 4; q++) {
                        float2 f = __half22float2(U0.h[q]);
                        s[2*q]   += w*f.x;
                        s[2*q+1] += w*f.y;
                    }
                    #pragma unroll
                    for (int q = 0; q < 4; q++) {
                        float2 f = __half22float2(U1.h[q]);
                        s[8+2*q]   += w*f.x;
                        s[8+2*q+1] += w*f.y;
                    }
                }
            }
        }
        const float* wrow = sW + n*C_;
        #pragma unroll
        for (int o = 0; o < OC_; o++) {
            float a = 0.f;
            #pragma unroll
            for (int c = 0; c < C_; c++) a += wrow[o*(N_*C_) + c] * s[c];
            acc[o] += a;
        }
    }

    // ReLU, then premultiply by this t's W_T slice (40x40), store h'.
    #pragma unroll
    for (int o = 0; o < OC_; o++) acc[o] = fmaxf(acc[o], 0.0f);

    float* hout = g_h + (size_t)pos * OC_;
    #pragma unroll
    for (int o0 = 0; o0 < OC_; o0 += 8) {
        float tmp[8];
        #pragma unroll
        for (int k = 0; k < 8; k++) tmp[k] = 0.f;
        #pragma unroll
        for (int oc = 0; oc < OC_; oc++) {
            float hv = acc[oc];
            #pragma unroll
            for (int k = 0; k < 8; k++) tmp[k] += sWT[(o0+k)*OC_ + oc] * hv;
        }
        #pragma unroll
        for (int k = 0; k < 8; k++) hout[o0+k] = tmp[k];
    }
}

// ---------------------------------------------------------------------------
// Kernel 2: per (b,dd,hh,wy): for each t, warp via cum matrix, trilinear-sample
// the 40 premultiplied channels of h', accumulate (+b_T), ReLU, write output.
// No GEMV here — linearity lets W_T commute with the warp.
// ---------------------------------------------------------------------------
__global__ void __launch_bounds__(128) k_warp(
    const float* __restrict__ b_T, float* __restrict__ out)
{
    __shared__ float sb[OC_];
    __shared__ float sC[T_*12];

    int pos = blockIdx.x*128 + threadIdx.x;     // 160000 total
    int b   = pos / VOXN;                       // block-uniform
    int rem = pos % VOXN;
    int wy  = rem % GY_;                        // Wp index
    int hh  = (rem / GY_) % GZ_;                // Hp index
    int dd  = rem / (GY_*GZ_);                  // Dp index

    if (threadIdx.x < OC_)    sb[threadIdx.x] = b_T[threadIdx.x];
    if (threadIdx.x < T_*12)  sC[threadIdx.x] = g_cum[b*T_*12 + threadIdx.x];
    __syncthreads();

    float bx = -1.0f + 2.0f*(float)wy / (float)(GY_-1);
    float by = -1.0f + 2.0f*(float)hh / (float)(GZ_-1);
    float bz = -1.0f + 2.0f*(float)dd / (float)(GX_-1);

    float acc[OC_];
    #pragma unroll
    for (int o = 0; o < OC_; o++) acc[o] = sb[o];

    for (int t = 0; t < T_; t++) {
        const float* th = sC + t*12;
        float gx = th[0]*bx + th[1]*by + th[2]*bz  + th[3];
        float gy = th[4]*bx + th[5]*by + th[6]*bz  + th[7];
        float gz = th[8]*bx + th[9]*by + th[10]*bz + th[11];
        float ix = (gx + 1.0f)*0.5f*(float)(GY_-1);   // Wp
        float iy = (gy + 1.0f)*0.5f*(float)(GZ_-1);   // Hp
        float iz = (gz + 1.0f)*0.5f*(float)(GX_-1);   // Dp
        ix = fminf(fmaxf(ix, -1.0e6f), 1.0e6f);
        iy = fminf(fmaxf(iy, -1.0e6f), 1.0e6f);
        iz = fminf(fmaxf(iz, -1.0e6f), 1.0e6f);

        float fx0 = floorf(ix), fy0 = floorf(iy), fz0 = floorf(iz);
        int x0 = (int)fx0, y0 = (int)fy0, z0 = (int)fz0;
        float wx1 = ix - fx0, wy1 = iy - fy0, wz1 = iz - fz0;

        const float* hb = g_h + (size_t)(b*T_+t)*VOXN*OC_;
        #pragma unroll
        for (int dz = 0; dz < 2; dz++) {
            int zi = z0 + dz;                       // Dp index
            if (zi < 0 || zi >= GX_) continue;
            float wz = dz ? wz1 : (1.0f - wz1);
            #pragma unroll
            for (int dy = 0; dy < 2; dy++) {
                int yi = y0 + dy;                   // Hp index
                if (yi < 0 || yi >= GZ_) continue;
                float wzy = wz * (dy ? wy1 : (1.0f - wy1));
                #pragma unroll
                for (int dx = 0; dx < 2; dx++) {
                    int xi = x0 + dx;               // Wp index
                    if (xi < 0 || xi >= GY_) continue;
                    float w = wzy * (dx ? wx1 : (1.0f - wx1));
                    const float4* p = reinterpret_cast<const float4*>(
                        hb + (size_t)(((zi*GZ_ + yi)*GY_) + xi)*OC_);
                    #pragma unroll
                    for (int q = 0; q < OC_/4; q++) {
                        float4 vq = p[q];
                        acc[q*4+0] += w*vq.x;
                        acc[q*4+1] += w*vq.y;
                        acc[q*4+2] += w*vq.z;
                        acc[q*4+3] += w*vq.w;
                    }
                }
            }
        }
    }

    // out[b][o][dd][hh][wy]
    #pragma unroll
    for (int o = 0; o < OC_; o++) {
        out[(((size_t)(b*OC_+o)*GX_ + dd)*GZ_ + hh)*GY_ + wy] = fmaxf(acc[o], 0.0f);
    }
}

// ---------------------------------------------------------------------------
extern "C" void kernel_launch(void* const* d_in, const int* in_sizes, int n_in,
                              void* d_out, int out_size) {
    const float* frustum = (const float*)d_in[0];
    const float* RT      = (const float*)d_in[1];
    const float* intrins = (const float*)d_in[2];
    const float* DoF     = (const float*)d_in[3];
    const float* W_N     = (const float*)d_in[4];
    const float* b_N     = (const float*)d_in[5];
    const float* W_T     = (const float*)d_in[6];
    const float* b_T     = (const float*)d_in[7];
    float* out = (float*)d_out;

    k_transpose<<<B_*T_*N_*FD_*FH_, 256>>>(frustum);
    k_cum<<<1, 32>>>(DoF);
    k_frustum<<<(B_*T_*VOXN)/128, 128>>>(RT, intrins, W_N, b_N, W_T);
    k_warp<<<(B_*VOXN)/128, 128>>>(b_T, out);
}

// round 10
// speedup vs baseline: 1.4979x; 1.3295x over previous
#include <cuda_runtime.h>
#include <cuda_bf16.h>
#include <cuda_fp16.h>
#include <math.h>

#define B_  2
#define T_  3
#define N_  6
#define C_  16
#define FD_ 48
#define FH_ 24
#define FW_ 64
#define GX_ 100
#define GY_ 100
#define GZ_ 8
#define OC_ 40
#define OP_ (OC_/2)                  // 20 output pairs

#define VOXN (GX_*GZ_*GY_)           // 80000 spatial positions per (b,t)
#define FEAT_PER_CAM (FD_*FH_*FW_*C_)

typedef unsigned long long u64;

// ---- packed-f32x2 helpers (FFMA2 — only reachable via PTX) --------------
__device__ __forceinline__ u64 pk2(float lo, float hi) {
    u64 r; asm("mov.b64 %0, {%1, %2};" : "=l"(r) : "f"(lo), "f"(hi)); return r;
}
__device__ __forceinline__ void upk2(u64 v, float& lo, float& hi) {
    asm("mov.b64 {%0, %1}, %2;" : "=f"(lo), "=f"(hi) : "l"(v));
}
__device__ __forceinline__ u64 f2fma(u64 a, u64 b, u64 c) {
    u64 d; asm("fma.rn.f32x2 %0, %1, %2, %3;" : "=l"(d) : "l"(a), "l"(b), "l"(c)); return d;
}

// Scratch (static device allocations — no cudaMalloc allowed)
__device__ __half g_featCL[(size_t)B_*T_*N_*FD_*FH_*FW_*C_]; // channel-last fp16 (~85MB)
__device__ __half g_h[(size_t)B_*T_*VOXN*OC_];               // W_T-premultiplied h', fp16 channel-last (~38MB)
__device__ float  g_cum[B_*T_*12];                           // top-3 rows of cumulative warp matrices

// ---------------------------------------------------------------------------
// Kernel 0: transpose frustum features [m][c][fd][fh][fw] -> [m][fd][fh][fw][c]
// fp32 in, fp16 out. One block per (m, fd, fh) row.
// ---------------------------------------------------------------------------
__global__ void k_transpose(const float* __restrict__ in) {
    __shared__ float tile[FW_*17];   // [fw][c], pad to kill bank conflicts
    int r  = blockIdx.x;                 // over B*T*N*FD*FH
    int m  = r / (FD_*FH_);
    int dh = r % (FD_*FH_);
    for (int idx = threadIdx.x; idx < C_*FW_; idx += blockDim.x) {
        int c  = idx / FW_;
        int fw = idx % FW_;
        tile[fw*17 + c] = in[(((size_t)m*C_ + c)*(FD_*FH_) + dh)*FW_ + fw];
    }
    __syncthreads();
    __half2* dst = reinterpret_cast<__half2*>(g_featCL + (size_t)r * (FW_*C_));
    for (int j = threadIdx.x; j < C_*FW_/2; j += blockDim.x) {
        int fw = j / (C_/2);
        int c  = (j % (C_/2)) * 2;
        dst[j] = __floats2half2_rn(tile[fw*17 + c], tile[fw*17 + c + 1]);
    }
}

// ---------------------------------------------------------------------------
// Cumulative warp matrices.  cum_{T-1}=I; cum_t = M4[t] @ cum_{t+1}
// ---------------------------------------------------------------------------
__global__ void k_cum(const float* __restrict__ DoF) {
    int b = threadIdx.x;
    if (b >= B_) return;
    float cum[16] = {1,0,0,0, 0,1,0,0, 0,0,1,0, 0,0,0,1};
    for (int t = T_-1; t >= 0; --t) {
        if (t < T_-1) {
            float M[16];
            #pragma unroll
            for (int i = 0; i < 3; i++)
                #pragma unroll
                for (int j = 0; j < 4; j++)
                    M[i*4+j] = DoF[((b*T_ + t)*4 + i)*4 + j];
            M[12]=0.f; M[13]=0.f; M[14]=0.f; M[15]=1.f;
            float nc[16];
            #pragma unroll
            for (int i = 0; i < 4; i++)
                #pragma unroll
                for (int j = 0; j < 4; j++) {
                    float a = 0.f;
                    #pragma unroll
                    for (int k = 0; k < 4; k++) a += M[i*4+k]*cum[k*4+j];
                    nc[i*4+j] = a;
                }
            #pragma unroll
            for (int i = 0; i < 16; i++) cum[i] = nc[i];
        }
        for (int i = 0; i < 12; i++) g_cum[(b*T_+t)*12 + i] = cum[i];
    }
}

// ---------------------------------------------------------------------------
// Kernel 1: per voxel (b,t,x,gz,gy): project into 6 cams, trilinear-sample 16
// fp16 channels, W_N (96->40) + b_N + ReLU, premultiply by per-t W_T slice,
// store h' channel-last fp16.  Both GEMVs run on packed fma.rn.f32x2.
// ---------------------------------------------------------------------------
__global__ void __launch_bounds__(128) k_frustum(
    const float* __restrict__ RT, const float* __restrict__ intr,
    const float* __restrict__ W_N, const float* __restrict__ b_N,
    const float* __restrict__ W_T)
{
    __shared__ float sP[N_*12];            // fused K @ RT[:3,:] per camera
    __shared__ u64   sW2[N_*C_*OP_];       // W_N packed by output pair [n][c][j]
    __shared__ u64   sWT2[OC_*OP_];        // per-t W_T slice packed [oc][j]
    __shared__ float sb[OC_];

    int pos = blockIdx.x*128 + threadIdx.x;     // 480000 total; VOXN%128==0
    int bt  = pos / VOXN;                       // block-uniform
    int t   = bt % T_;
    int b   = bt / T_;
    int rem = pos % VOXN;
    int gy  = rem % GY_;
    int gz  = (rem / GY_) % GZ_;
    int x   = rem / (GY_*GZ_);

    for (int i = threadIdx.x; i < N_*C_*OP_; i += 128) {
        int j = i % OP_;
        int nc = i / OP_;                 // n*C_+c
        sW2[i] = pk2(W_N[(2*j)*(N_*C_) + nc], W_N[(2*j+1)*(N_*C_) + nc]);
    }
    for (int i = threadIdx.x; i < OC_*OP_; i += 128) {
        int j  = i % OP_;
        int oc = i / OP_;
        sWT2[i] = pk2(W_T[(2*j)*(T_*OC_) + t*OC_ + oc],
                      W_T[(2*j+1)*(T_*OC_) + t*OC_ + oc]);
    }
    if (threadIdx.x < OC_) sb[threadIdx.x] = b_N[threadIdx.x];
    if (threadIdx.x < N_) {
        const float* K = intr + b*9;
        const float* R = RT + ((size_t)((b*T_+t)*N_ + threadIdx.x))*16;
        #pragma unroll
        for (int i = 0; i < 3; i++)
            #pragma unroll
            for (int j = 0; j < 4; j++)
                sP[threadIdx.x*12 + i*4 + j] =
                    K[i*3+0]*R[0*4+j] + K[i*3+1]*R[1*4+j] + K[i*3+2]*R[2*4+j];
    }
    __syncthreads();

    float px = -50.0f + ((float)x  + 0.5f);
    float py = -50.0f + ((float)gy + 0.5f);
    float pz = -3.0f  + ((float)gz + 0.5f);

    u64 acc2[OP_];
    #pragma unroll
    for (int j = 0; j < OP_; j++) acc2[j] = pk2(sb[2*j], sb[2*j+1]);

    for (int n = 0; n < N_; n++) {
        const float* P = sP + n*12;
        float pr0 = P[0]*px + P[1]*py + P[2]*pz  + P[3];
        float pr1 = P[4]*px + P[5]*py + P[6]*pz  + P[7];
        float pr2 = P[8]*px + P[9]*py + P[10]*pz + P[11];
        float zc = fmaxf(pr2, 1e-5f);
        float u = pr0 / zc;
        float v = pr1 / zc;
        float d = (pr2 - 2.0f) / ((46.8f - 2.0f) / 48.0f);
        u = fminf(fmaxf(u, -1.0e6f), 1.0e6f);
        v = fminf(fmaxf(v, -1.0e6f), 1.0e6f);
        d = fminf(fmaxf(d, -1.0e6f), 1.0e6f);

        float fx0 = floorf(u), fy0 = floorf(v), fz0 = floorf(d);
        int x0 = (int)fx0, y0 = (int)fy0, z0 = (int)fz0;
        float wx1 = u - fx0, wy1 = v - fy0, wz1 = d - fz0;

        float s[C_];
        #pragma unroll
        for (int c = 0; c < C_; c++) s[c] = 0.f;

        const __half* fb = g_featCL + (size_t)((b*T_+t)*N_ + n)*FEAT_PER_CAM;
        #pragma unroll
        for (int dz = 0; dz < 2; dz++) {
            int zi = z0 + dz;
            if (zi < 0 || zi >= FD_) continue;
            float wz = dz ? wz1 : (1.0f - wz1);
            #pragma unroll
            for (int dy = 0; dy < 2; dy++) {
                int yi = y0 + dy;
                if (yi < 0 || yi >= FH_) continue;
                float wzy = wz * (dy ? wy1 : (1.0f - wy1));
                #pragma unroll
                for (int dx = 0; dx < 2; dx++) {
                    int xi = x0 + dx;
                    if (xi < 0 || xi >= FW_) continue;
                    float w = wzy * (dx ? wx1 : (1.0f - wx1));
                    union { uint4 u4; __half2 h[8]; } U0, U1;
                    const uint4* p = reinterpret_cast<const uint4*>(
                        fb + (size_t)((zi*FH_ + yi)*FW_ + xi)*C_);
                    U0.u4 = p[0]; U1.u4 = p[1];
                    #pragma unroll
                    for (int q = 0; q < 4; q++) {
                        float2 f = __half22float2(U0.h[q]);
                        s[2*q]   += w*f.x;
                        s[2*q+1] += w*f.y;
                    }
                    #pragma unroll
                    for (int q = 0; q < 4; q++) {
                        float2 f = __half22float2(U1.h[q]);
                        s[8+2*q]   += w*f.x;
                        s[8+2*q+1] += w*f.y;
                    }
                }
            }
        }
        // packed GEMV: acc2 += W_N[:, n*16+c] * s[c]
        const u64* wp = sW2 + n*C_*OP_;
        #pragma unroll
        for (int c = 0; c < C_; c++) {
            u64 bb = pk2(s[c], s[c]);
            #pragma unroll
            for (int j = 0; j < OP_; j++)
                acc2[j] = f2fma(wp[c*OP_ + j], bb, acc2[j]);
        }
    }

    // ReLU
    float h[OC_];
    #pragma unroll
    for (int j = 0; j < OP_; j++) {
        float lo, hi; upk2(acc2[j], lo, hi);
        h[2*j]   = fmaxf(lo, 0.0f);
        h[2*j+1] = fmaxf(hi, 0.0f);
    }

    // packed premultiply by this t's W_T slice (40x40)
    u64 out2[OP_];
    #pragma unroll
    for (int j = 0; j < OP_; j++) out2[j] = 0ull;
    #pragma unroll
    for (int oc = 0; oc < OC_; oc++) {
        u64 bb = pk2(h[oc], h[oc]);
        const u64* wp = sWT2 + oc*OP_;
        #pragma unroll
        for (int j = 0; j < OP_; j++)
            out2[j] = f2fma(wp[j], bb, out2[j]);
    }

    // store fp16 h'
    union { uint4 q[5]; __half2 h2[OP_]; } O;
    #pragma unroll
    for (int j = 0; j < OP_; j++) {
        float lo, hi; upk2(out2[j], lo, hi);
        O.h2[j] = __floats2half2_rn(lo, hi);
    }
    uint4* dst = reinterpret_cast<uint4*>(g_h + (size_t)pos * OC_);
    #pragma unroll
    for (int q = 0; q < 5; q++) dst[q] = O.q[q];
}

// ---------------------------------------------------------------------------
// Kernel 2: per (b,dd,hh,wy): for each t, warp via cum matrix, trilinear-sample
// the 40 premultiplied fp16 channels of h', accumulate (+b_T), ReLU, write out.
// ---------------------------------------------------------------------------
__global__ void __launch_bounds__(128) k_warp(
    const float* __restrict__ b_T, float* __restrict__ out)
{
    __shared__ float sb[OC_];
    __shared__ float sC[T_*12];

    int pos = blockIdx.x*128 + threadIdx.x;     // 160000 total
    int b   = pos / VOXN;                       // block-uniform
    int rem = pos % VOXN;
    int wy  = rem % GY_;                        // Wp index
    int hh  = (rem / GY_) % GZ_;                // Hp index
    int dd  = rem / (GY_*GZ_);                  // Dp index

    if (threadIdx.x < OC_)    sb[threadIdx.x] = b_T[threadIdx.x];
    if (threadIdx.x < T_*12)  sC[threadIdx.x] = g_cum[b*T_*12 + threadIdx.x];
    __syncthreads();

    float bx = -1.0f + 2.0f*(float)wy / (float)(GY_-1);
    float by = -1.0f + 2.0f*(float)hh / (float)(GZ_-1);
    float bz = -1.0f + 2.0f*(float)dd / (float)(GX_-1);

    u64 acc2[OP_];
    #pragma unroll
    for (int j = 0; j < OP_; j++) acc2[j] = pk2(sb[2*j], sb[2*j+1]);

    for (int t = 0; t < T_; t++) {
        const float* th = sC + t*12;
        float gx = th[0]*bx + th[1]*by + th[2]*bz  + th[3];
        float gy = th[4]*bx + th[5]*by + th[6]*bz  + th[7];
        float gz = th[8]*bx + th[9]*by + th[10]*bz + th[11];
        float ix = (gx + 1.0f)*0.5f*(float)(GY_-1);   // Wp
        float iy = (gy + 1.0f)*0.5f*(float)(GZ_-1);   // Hp
        float iz = (gz + 1.0f)*0.5f*(float)(GX_-1);   // Dp
        ix = fminf(fmaxf(ix, -1.0e6f), 1.0e6f);
        iy = fminf(fmaxf(iy, -1.0e6f), 1.0e6f);
        iz = fminf(fmaxf(iz, -1.0e6f), 1.0e6f);

        float fx0 = floorf(ix), fy0 = floorf(iy), fz0 = floorf(iz);
        int x0 = (int)fx0, y0 = (int)fy0, z0 = (int)fz0;
        float wx1 = ix - fx0, wy1 = iy - fy0, wz1 = iz - fz0;

        const __half* hb = g_h + (size_t)(b*T_+t)*VOXN*OC_;
        #pragma unroll
        for (int dz = 0; dz < 2; dz++) {
            int zi = z0 + dz;                       // Dp index
            if (zi < 0 || zi >= GX_) continue;
            float wz = dz ? wz1 : (1.0f - wz1);
            #pragma unroll
            for (int dy = 0; dy < 2; dy++) {
                int yi = y0 + dy;                   // Hp index
                if (yi < 0 || yi >= GZ_) continue;
                float wzy = wz * (dy ? wy1 : (1.0f - wy1));
                #pragma unroll
                for (int dx = 0; dx < 2; dx++) {
                    int xi = x0 + dx;               // Wp index
                    if (xi < 0 || xi >= GY_) continue;
                    float w = wzy * (dx ? wx1 : (1.0f - wx1));
                    u64 ww = pk2(w, w);
                    const uint4* p = reinterpret_cast<const uint4*>(
                        hb + (size_t)(((zi*GZ_ + yi)*GY_) + xi)*OC_);
                    #pragma unroll
                    for (int q = 0; q < 5; q++) {
                        union { uint4 u4; __half2 h[4]; } U;
                        U.u4 = p[q];
                        #pragma unroll
                        for (int k = 0; k < 4; k++) {
                            float2 f = __half22float2(U.h[k]);
                            acc2[q*4+k] = f2fma(pk2(f.x, f.y), ww, acc2[q*4+k]);
                        }
                    }
                }
            }
        }
    }

    // out[b][o][dd][hh][wy]
    #pragma unroll
    for (int j = 0; j < OP_; j++) {
        float lo, hi; upk2(acc2[j], lo, hi);
        out[(((size_t)(b*OC_ + 2*j  )*GX_ + dd)*GZ_ + hh)*GY_ + wy] = fmaxf(lo, 0.0f);
        out[(((size_t)(b*OC_ + 2*j+1)*GX_ + dd)*GZ_ + hh)*GY_ + wy] = fmaxf(hi, 0.0f);
    }
}

// ---------------------------------------------------------------------------
extern "C" void kernel_launch(void* const* d_in, const int* in_sizes, int n_in,
                              void* d_out, int out_size) {
    const float* frustum = (const float*)d_in[0];
    const float* RT      = (const float*)d_in[1];
    const float* intrins = (const float*)d_in[2];
    const float* DoF     = (const float*)d_in[3];
    const float* W_N     = (const float*)d_in[4];
    const float* b_N     = (const float*)d_in[5];
    const float* W_T     = (const float*)d_in[6];
    const float* b_T     = (const float*)d_in[7];
    float* out = (float*)d_out;

    k_transpose<<<B_*T_*N_*FD_*FH_, 256>>>(frustum);
    k_cum<<<1, 32>>>(DoF);
    k_frustum<<<(B_*T_*VOXN)/128, 128>>>(RT, intrins, W_N, b_N, W_T);
    k_warp<<<(B_*VOXN)/128, 128>>>(b_T, out);
}

// round 11
// speedup vs baseline: 1.8195x; 1.2147x over previous
#include <cuda_runtime.h>
#include <cuda_bf16.h>
#include <cuda_fp16.h>
#include <math.h>

#define B_  2
#define T_  3
#define N_  6
#define C_  16
#define FD_ 48
#define FH_ 24
#define FW_ 64
#define GX_ 100
#define GY_ 100
#define GZ_ 8
#define OC_ 40
#define OP_ (OC_/2)                  // 20 output pairs

#define VOXN (GX_*GZ_*GY_)           // 80000 spatial positions per (b,t)
#define FEAT_PER_CAM (FD_*FH_*FW_*C_)

typedef unsigned long long u64;

// ---- packed-f32x2 helpers (FFMA2 — only reachable via PTX) --------------
__device__ __forceinline__ u64 pk2(float lo, float hi) {
    u64 r; asm("mov.b64 %0, {%1, %2};" : "=l"(r) : "f"(lo), "f"(hi)); return r;
}
__device__ __forceinline__ void upk2(u64 v, float& lo, float& hi) {
    asm("mov.b64 {%0, %1}, %2;" : "=f"(lo), "=f"(hi) : "l"(v));
}
__device__ __forceinline__ u64 f2fma(u64 a, u64 b, u64 c) {
    u64 d; asm("fma.rn.f32x2 %0, %1, %2, %3;" : "=l"(d) : "l"(a), "l"(b), "l"(c)); return d;
}

// Scratch (static device allocations — no cudaMalloc allowed)
__device__ __half g_featCL[(size_t)B_*T_*N_*FD_*FH_*FW_*C_]; // channel-last fp16 (~85MB)
__device__ __half g_h[(size_t)B_*T_*VOXN*OC_];               // W_T-premultiplied h', fp16 channel-last (~38MB)
__device__ float  g_cum[B_*T_*12];                           // top-3 rows of cumulative warp matrices

// ---------------------------------------------------------------------------
// Kernel 0: transpose frustum features [m][c][fd][fh][fw] -> [m][fd][fh][fw][c]
// fp32 in, fp16 out. One block per (m, fd, fh) row.
// ---------------------------------------------------------------------------
__global__ void k_transpose(const float* __restrict__ in) {
    __shared__ float tile[FW_*17];   // [fw][c], pad to kill bank conflicts
    int r  = blockIdx.x;                 // over B*T*N*FD*FH
    int m  = r / (FD_*FH_);
    int dh = r % (FD_*FH_);
    for (int idx = threadIdx.x; idx < C_*FW_; idx += blockDim.x) {
        int c  = idx / FW_;
        int fw = idx % FW_;
        tile[fw*17 + c] = in[(((size_t)m*C_ + c)*(FD_*FH_) + dh)*FW_ + fw];
    }
    __syncthreads();
    __half2* dst = reinterpret_cast<__half2*>(g_featCL + (size_t)r * (FW_*C_));
    for (int j = threadIdx.x; j < C_*FW_/2; j += blockDim.x) {
        int fw = j / (C_/2);
        int c  = (j % (C_/2)) * 2;
        dst[j] = __floats2half2_rn(tile[fw*17 + c], tile[fw*17 + c + 1]);
    }
}

// ---------------------------------------------------------------------------
// Cumulative warp matrices.  cum_{T-1}=I; cum_t = M4[t] @ cum_{t+1}
// ---------------------------------------------------------------------------
__global__ void k_cum(const float* __restrict__ DoF) {
    int b = threadIdx.x;
    if (b >= B_) return;
    float cum[16] = {1,0,0,0, 0,1,0,0, 0,0,1,0, 0,0,0,1};
    for (int t = T_-1; t >= 0; --t) {
        if (t < T_-1) {
            float M[16];
            #pragma unroll
            for (int i = 0; i < 3; i++)
                #pragma unroll
                for (int j = 0; j < 4; j++)
                    M[i*4+j] = DoF[((b*T_ + t)*4 + i)*4 + j];
            M[12]=0.f; M[13]=0.f; M[14]=0.f; M[15]=1.f;
            float nc[16];
            #pragma unroll
            for (int i = 0; i < 4; i++)
                #pragma unroll
                for (int j = 0; j < 4; j++) {
                    float a = 0.f;
                    #pragma unroll
                    for (int k = 0; k < 4; k++) a += M[i*4+k]*cum[k*4+j];
                    nc[i*4+j] = a;
                }
            #pragma unroll
            for (int i = 0; i < 16; i++) cum[i] = nc[i];
        }
        for (int i = 0; i < 12; i++) g_cum[(b*T_+t)*12 + i] = cum[i];
    }
}

// ---------------------------------------------------------------------------
// Kernel 1: per voxel (b,t,x,gz,gy): project into 6 cams, trilinear-sample 16
// fp16 channels, W_N (96->40) + b_N + ReLU, premultiply by per-t W_T slice,
// store h' channel-last fp16.  GEMVs on fma.rn.f32x2 with LDS.128 weight
// loads; trilinear accumulate also packed; branchless corner masking.
// ---------------------------------------------------------------------------
__global__ void __launch_bounds__(128) k_frustum(
    const float* __restrict__ RT, const float* __restrict__ intr,
    const float* __restrict__ W_N, const float* __restrict__ b_N,
    const float* __restrict__ W_T)
{
    __shared__ float sP[N_*12];                       // fused K @ RT[:3,:]
    __shared__ __align__(16) u64 sW2[N_*C_*OP_];      // W_N packed [n][c][j]
    __shared__ __align__(16) u64 sWT2[OC_*OP_];       // per-t W_T slice [oc][j]
    __shared__ float sb[OC_];

    int pos = blockIdx.x*128 + threadIdx.x;     // 480000 total; VOXN%128==0
    int bt  = pos / VOXN;                       // block-uniform
    int t   = bt % T_;
    int b   = bt / T_;
    int rem = pos % VOXN;
    int gy  = rem % GY_;
    int gz  = (rem / GY_) % GZ_;
    int x   = rem / (GY_*GZ_);

    for (int i = threadIdx.x; i < N_*C_*OP_; i += 128) {
        int j = i % OP_;
        int nc = i / OP_;                 // n*C_+c
        sW2[i] = pk2(W_N[(2*j)*(N_*C_) + nc], W_N[(2*j+1)*(N_*C_) + nc]);
    }
    for (int i = threadIdx.x; i < OC_*OP_; i += 128) {
        int j  = i % OP_;
        int oc = i / OP_;
        sWT2[i] = pk2(W_T[(2*j)*(T_*OC_) + t*OC_ + oc],
                      W_T[(2*j+1)*(T_*OC_) + t*OC_ + oc]);
    }
    if (threadIdx.x < OC_) sb[threadIdx.x] = b_N[threadIdx.x];
    if (threadIdx.x < N_) {
        const float* K = intr + b*9;
        const float* R = RT + ((size_t)((b*T_+t)*N_ + threadIdx.x))*16;
        #pragma unroll
        for (int i = 0; i < 3; i++)
            #pragma unroll
            for (int j = 0; j < 4; j++)
                sP[threadIdx.x*12 + i*4 + j] =
                    K[i*3+0]*R[0*4+j] + K[i*3+1]*R[1*4+j] + K[i*3+2]*R[2*4+j];
    }
    __syncthreads();

    float px = -50.0f + ((float)x  + 0.5f);
    float py = -50.0f + ((float)gy + 0.5f);
    float pz = -3.0f  + ((float)gz + 0.5f);

    u64 acc2[OP_];
    #pragma unroll
    for (int j = 0; j < OP_; j++) acc2[j] = pk2(sb[2*j], sb[2*j+1]);

    for (int n = 0; n < N_; n++) {
        const float* P = sP + n*12;
        float pr0 = P[0]*px + P[1]*py + P[2]*pz  + P[3];
        float pr1 = P[4]*px + P[5]*py + P[6]*pz  + P[7];
        float pr2 = P[8]*px + P[9]*py + P[10]*pz + P[11];
        float zc = fmaxf(pr2, 1e-5f);
        float u = pr0 / zc;
        float v = pr1 / zc;
        float d = (pr2 - 2.0f) / ((46.8f - 2.0f) / 48.0f);
        u = fminf(fmaxf(u, -1.0e6f), 1.0e6f);
        v = fminf(fmaxf(v, -1.0e6f), 1.0e6f);
        d = fminf(fmaxf(d, -1.0e6f), 1.0e6f);

        float fx0 = floorf(u), fy0 = floorf(v), fz0 = floorf(d);
        int x0 = (int)fx0, y0 = (int)fy0, z0 = (int)fz0;
        // fully outside -> zero contribution (GEMV of zeros) -> skip camera
        if (x0 < -1 || x0 > FW_-1 || y0 < -1 || y0 > FH_-1 ||
            z0 < -1 || z0 > FD_-1) continue;

        float wx1 = u - fx0, wy1 = v - fy0, wz1 = d - fz0;
        // masked weights (exact zeros for invalid sides) + clamped indices
        float wxm[2] = { (1.0f-wx1) * (float)(x0 >= 0), wx1 * (float)(x0 < FW_-1) };
        float wym[2] = { (1.0f-wy1) * (float)(y0 >= 0), wy1 * (float)(y0 < FH_-1) };
        float wzm[2] = { (1.0f-wz1) * (float)(z0 >= 0), wz1 * (float)(z0 < FD_-1) };
        int xc[2] = { max(x0, 0), min(x0+1, FW_-1) };
        int yc[2] = { max(y0, 0), min(y0+1, FH_-1) };
        int zcl[2] = { max(z0, 0), min(z0+1, FD_-1) };

        u64 s2[8];
        #pragma unroll
        for (int q = 0; q < 8; q++) s2[q] = 0ull;

        const __half* fb = g_featCL + (size_t)((b*T_+t)*N_ + n)*FEAT_PER_CAM;
        #pragma unroll
        for (int dz = 0; dz < 2; dz++) {
            #pragma unroll
            for (int dy = 0; dy < 2; dy++) {
                float wzy = wzm[dz]*wym[dy];
                int row = (zcl[dz]*FH_ + yc[dy])*FW_;
                #pragma unroll
                for (int dx = 0; dx < 2; dx++) {
                    float w = wzy*wxm[dx];
                    u64 ww = pk2(w, w);
                    union { uint4 u4; __half2 h[4]; } U0, U1;
                    const uint4* p = reinterpret_cast<const uint4*>(
                        fb + (size_t)(row + xc[dx])*C_);
                    U0.u4 = p[0]; U1.u4 = p[1];
                    #pragma unroll
                    for (int q = 0; q < 4; q++) {
                        float2 f0 = __half22float2(U0.h[q]);
                        s2[q]   = f2fma(pk2(f0.x, f0.y), ww, s2[q]);
                        float2 f1 = __half22float2(U1.h[q]);
                        s2[4+q] = f2fma(pk2(f1.x, f1.y), ww, s2[4+q]);
                    }
                }
            }
        }
        float s[C_];
        #pragma unroll
        for (int q = 0; q < 8; q++) upk2(s2[q], s[2*q], s[2*q+1]);

        // packed GEMV: acc2 += W_N[:, n*16+c] * s[c]   (LDS.128 weight loads)
        const ulonglong2* wp = reinterpret_cast<const ulonglong2*>(sW2 + n*C_*OP_);
        #pragma unroll
        for (int c = 0; c < C_; c++) {
            u64 bb = pk2(s[c], s[c]);
            #pragma unroll
            for (int q = 0; q < OP_/2; q++) {
                ulonglong2 wv = wp[c*(OP_/2) + q];
                acc2[2*q]   = f2fma(wv.x, bb, acc2[2*q]);
                acc2[2*q+1] = f2fma(wv.y, bb, acc2[2*q+1]);
            }
        }
    }

    // ReLU
    float h[OC_];
    #pragma unroll
    for (int j = 0; j < OP_; j++) {
        float lo, hi; upk2(acc2[j], lo, hi);
        h[2*j]   = fmaxf(lo, 0.0f);
        h[2*j+1] = fmaxf(hi, 0.0f);
    }

    // packed premultiply by this t's W_T slice (40x40), LDS.128 weights
    u64 out2[OP_];
    #pragma unroll
    for (int j = 0; j < OP_; j++) out2[j] = 0ull;
    const ulonglong2* wq = reinterpret_cast<const ulonglong2*>(sWT2);
    #pragma unroll
    for (int oc = 0; oc < OC_; oc++) {
        u64 bb = pk2(h[oc], h[oc]);
        #pragma unroll
        for (int q = 0; q < OP_/2; q++) {
            ulonglong2 wv = wq[oc*(OP_/2) + q];
            out2[2*q]   = f2fma(wv.x, bb, out2[2*q]);
            out2[2*q+1] = f2fma(wv.y, bb, out2[2*q+1]);
        }
    }

    // store fp16 h'
    union { uint4 q[5]; __half2 h2[OP_]; } O;
    #pragma unroll
    for (int j = 0; j < OP_; j++) {
        float lo, hi; upk2(out2[j], lo, hi);
        O.h2[j] = __floats2half2_rn(lo, hi);
    }
    uint4* dst = reinterpret_cast<uint4*>(g_h + (size_t)pos * OC_);
    #pragma unroll
    for (int q = 0; q < 5; q++) dst[q] = O.q[q];
}

// ---------------------------------------------------------------------------
// Kernel 2: per (b,dd,hh,wy): for each t, warp via cum matrix, trilinear-sample
// the 40 premultiplied fp16 channels of h', accumulate (+b_T), ReLU, write out.
// ---------------------------------------------------------------------------
__global__ void __launch_bounds__(128) k_warp(
    const float* __restrict__ b_T, float* __restrict__ out)
{
    __shared__ float sb[OC_];
    __shared__ float sC[T_*12];

    int pos = blockIdx.x*128 + threadIdx.x;     // 160000 total
    int b   = pos / VOXN;                       // block-uniform
    int rem = pos % VOXN;
    int wy  = rem % GY_;                        // Wp index
    int hh  = (rem / GY_) % GZ_;                // Hp index
    int dd  = rem / (GY_*GZ_);                  // Dp index

    if (threadIdx.x < OC_)    sb[threadIdx.x] = b_T[threadIdx.x];
    if (threadIdx.x < T_*12)  sC[threadIdx.x] = g_cum[b*T_*12 + threadIdx.x];
    __syncthreads();

    float bx = -1.0f + 2.0f*(float)wy / (float)(GY_-1);
    float by = -1.0f + 2.0f*(float)hh / (float)(GZ_-1);
    float bz = -1.0f + 2.0f*(float)dd / (float)(GX_-1);

    u64 acc2[OP_];
    #pragma unroll
    for (int j = 0; j < OP_; j++) acc2[j] = pk2(sb[2*j], sb[2*j+1]);

    for (int t = 0; t < T_; t++) {
        const float* th = sC + t*12;
        float gx = th[0]*bx + th[1]*by + th[2]*bz  + th[3];
        float gy = th[4]*bx + th[5]*by + th[6]*bz  + th[7];
        float gz = th[8]*bx + th[9]*by + th[10]*bz + th[11];
        float ix = (gx + 1.0f)*0.5f*(float)(GY_-1);   // Wp
        float iy = (gy + 1.0f)*0.5f*(float)(GZ_-1);   // Hp
        float iz = (gz + 1.0f)*0.5f*(float)(GX_-1);   // Dp
        ix = fminf(fmaxf(ix, -1.0e6f), 1.0e6f);
        iy = fminf(fmaxf(iy, -1.0e6f), 1.0e6f);
        iz = fminf(fmaxf(iz, -1.0e6f), 1.0e6f);

        float fx0 = floorf(ix), fy0 = floorf(iy), fz0 = floorf(iz);
        int x0 = (int)fx0, y0 = (int)fy0, z0 = (int)fz0;
        if (x0 < -1 || x0 > GY_-1 || y0 < -1 || y0 > GZ_-1 ||
            z0 < -1 || z0 > GX_-1) continue;

        float wx1 = ix - fx0, wy1 = iy - fy0, wz1 = iz - fz0;
        float wxm[2] = { (1.0f-wx1) * (float)(x0 >= 0), wx1 * (float)(x0 < GY_-1) };
        float wym[2] = { (1.0f-wy1) * (float)(y0 >= 0), wy1 * (float)(y0 < GZ_-1) };
        float wzm[2] = { (1.0f-wz1) * (float)(z0 >= 0), wz1 * (float)(z0 < GX_-1) };
        int xc[2]  = { max(x0, 0), min(x0+1, GY_-1) };
        int yc[2]  = { max(y0, 0), min(y0+1, GZ_-1) };
        int zcl[2] = { max(z0, 0), min(z0+1, GX_-1) };

        const __half* hb = g_h + (size_t)(b*T_+t)*VOXN*OC_;
        #pragma unroll
        for (int dz = 0; dz < 2; dz++) {
            #pragma unroll
            for (int dy = 0; dy < 2; dy++) {
                float wzy = wzm[dz]*wym[dy];
                int row = (zcl[dz]*GZ_ + yc[dy])*GY_;
                #pragma unroll
                for (int dx = 0; dx < 2; dx++) {
                    float w = wzy*wxm[dx];
                    u64 ww = pk2(w, w);
                    const uint4* p = reinterpret_cast<const uint4*>(
                        hb + (size_t)(row + xc[dx])*OC_);
                    #pragma unroll
                    for (int q = 0; q < 5; q++) {
                        union { uint4 u4; __half2 h[4]; } U;
                        U.u4 = p[q];
                        #pragma unroll
                        for (int k = 0; k < 4; k++) {
                            float2 f = __half22float2(U.h[k]);
                            acc2[q*4+k] = f2fma(pk2(f.x, f.y), ww, acc2[q*4+k]);
                        }
                    }
                }
            }
        }
    }

    // out[b][o][dd][hh][wy]
    #pragma unroll
    for (int j = 0; j < OP_; j++) {
        float lo, hi; upk2(acc2[j], lo, hi);
        out[(((size_t)(b*OC_ + 2*j  )*GX_ + dd)*GZ_ + hh)*GY_ + wy] = fmaxf(lo, 0.0f);
        out[(((size_t)(b*OC_ + 2*j+1)*GX_ + dd)*GZ_ + hh)*GY_ + wy] = fmaxf(hi, 0.0f);
    }
}

// ---------------------------------------------------------------------------
extern "C" void kernel_launch(void* const* d_in, const int* in_sizes, int n_in,
                              void* d_out, int out_size) {
    const float* frustum = (const float*)d_in[0];
    const float* RT      = (const float*)d_in[1];
    const float* intrins = (const float*)d_in[2];
    const float* DoF     = (const float*)d_in[3];
    const float* W_N     = (const float*)d_in[4];
    const float* b_N     = (const float*)d_in[5];
    const float* W_T     = (const float*)d_in[6];
    const float* b_T     = (const float*)d_in[7];
    float* out = (float*)d_out;

    k_transpose<<<B_*T_*N_*FD_*FH_, 256>>>(frustum);
    k_cum<<<1, 32>>>(DoF);
    k_frustum<<<(B_*T_*VOXN)/128, 128>>>(RT, intrins, W_N, b_N, W_T);
    k_warp<<<(B_*VOXN)/128, 128>>>(b_T, out);
}

// round 12
// speedup vs baseline: 1.8226x; 1.0017x over previous
#include <cuda_runtime.h>
#include <cuda_bf16.h>
#include <cuda_fp16.h>
#include <math.h>

#define B_  2
#define T_  3
#define N_  6
#define C_  16
#define FD_ 48
#define FH_ 24
#define FW_ 64
#define GX_ 100
#define GY_ 100
#define GZ_ 8
#define OC_ 40
#define OP_ (OC_/2)                  // 20 output pairs

#define VOXN (GX_*GZ_*GY_)           // 80000 spatial positions per (b,t)
#define FEAT_PER_CAM (FD_*FH_*FW_*C_)

typedef unsigned long long u64;

// ---- packed-f32x2 helpers (FFMA2 — only reachable via PTX) --------------
__device__ __forceinline__ u64 pk2(float lo, float hi) {
    u64 r; asm("mov.b64 %0, {%1, %2};" : "=l"(r) : "f"(lo), "f"(hi)); return r;
}
__device__ __forceinline__ void upk2(u64 v, float& lo, float& hi) {
    asm("mov.b64 {%0, %1}, %2;" : "=f"(lo), "=f"(hi) : "l"(v));
}
__device__ __forceinline__ u64 f2fma(u64 a, u64 b, u64 c) {
    u64 d; asm("fma.rn.f32x2 %0, %1, %2, %3;" : "=l"(d) : "l"(a), "l"(b), "l"(c)); return d;
}

// Scratch (static device allocations — no cudaMalloc allowed)
__device__ __half g_featCL[(size_t)B_*T_*N_*FD_*FH_*FW_*C_]; // channel-last fp16 (~85MB)
__device__ __half g_h[(size_t)B_*T_*VOXN*OC_];               // W_T-premultiplied h', fp16 channel-last (~38MB)
__device__ float  g_cum[B_*T_*12];                           // top-3 rows of cumulative warp matrices

// ---------------------------------------------------------------------------
// Kernel 0: transpose frustum features [m][c][fd][fh][fw] -> [m][fd][fh][fw][c]
// fp32 in, fp16 out. One block per (m, fd, fh) row.
// ---------------------------------------------------------------------------
__global__ void k_transpose(const float* __restrict__ in) {
    __shared__ float tile[FW_*17];   // [fw][c], pad to kill bank conflicts
    int r  = blockIdx.x;                 // over B*T*N*FD*FH
    int m  = r / (FD_*FH_);
    int dh = r % (FD_*FH_);
    for (int idx = threadIdx.x; idx < C_*FW_; idx += blockDim.x) {
        int c  = idx / FW_;
        int fw = idx % FW_;
        tile[fw*17 + c] = in[(((size_t)m*C_ + c)*(FD_*FH_) + dh)*FW_ + fw];
    }
    __syncthreads();
    __half2* dst = reinterpret_cast<__half2*>(g_featCL + (size_t)r * (FW_*C_));
    for (int j = threadIdx.x; j < C_*FW_/2; j += blockDim.x) {
        int fw = j / (C_/2);
        int c  = (j % (C_/2)) * 2;
        dst[j] = __floats2half2_rn(tile[fw*17 + c], tile[fw*17 + c + 1]);
    }
}

// ---------------------------------------------------------------------------
// Cumulative warp matrices.  cum_{T-1}=I; cum_t = M4[t] @ cum_{t+1}
// ---------------------------------------------------------------------------
__global__ void k_cum(const float* __restrict__ DoF) {
    int b = threadIdx.x;
    if (b >= B_) return;
    float cum[16] = {1,0,0,0, 0,1,0,0, 0,0,1,0, 0,0,0,1};
    for (int t = T_-1; t >= 0; --t) {
        if (t < T_-1) {
            float M[16];
            #pragma unroll
            for (int i = 0; i < 3; i++)
                #pragma unroll
                for (int j = 0; j < 4; j++)
                    M[i*4+j] = DoF[((b*T_ + t)*4 + i)*4 + j];
            M[12]=0.f; M[13]=0.f; M[14]=0.f; M[15]=1.f;
            float nc[16];
            #pragma unroll
            for (int i = 0; i < 4; i++)
                #pragma unroll
                for (int j = 0; j < 4; j++) {
                    float a = 0.f;
                    #pragma unroll
                    for (int k = 0; k < 4; k++) a += M[i*4+k]*cum[k*4+j];
                    nc[i*4+j] = a;
                }
            #pragma unroll
            for (int i = 0; i < 16; i++) cum[i] = nc[i];
        }
        for (int i = 0; i < 12; i++) g_cum[(b*T_+t)*12 + i] = cum[i];
    }
}

// ---------------------------------------------------------------------------
// Kernel 1: per voxel (b,t,x,gz,gy): project into 6 cams, trilinear-sample 16
// fp16 channels, W_N (96->40) + b_N + ReLU, premultiply by per-t W_T slice,
// store h' channel-last fp16.  GEMVs on fma.rn.f32x2 with LDS.128 weight
// loads; trilinear accumulate also packed; branchless corner masking.
// ---------------------------------------------------------------------------
__global__ void __launch_bounds__(128) k_frustum(
    const float* __restrict__ RT, const float* __restrict__ intr,
    const float* __restrict__ W_N, const float* __restrict__ b_N,
    const float* __restrict__ W_T)
{
    __shared__ float sP[N_*12];                       // fused K @ RT[:3,:]
    __shared__ __align__(16) u64 sW2[N_*C_*OP_];      // W_N packed [n][c][j]
    __shared__ __align__(16) u64 sWT2[OC_*OP_];       // per-t W_T slice [oc][j]
    __shared__ float sb[OC_];

    int pos = blockIdx.x*128 + threadIdx.x;     // 480000 total; VOXN%128==0
    int bt  = pos / VOXN;                       // block-uniform
    int t   = bt % T_;
    int b   = bt / T_;
    int rem = pos % VOXN;
    int gy  = rem % GY_;
    int gz  = (rem / GY_) % GZ_;
    int x   = rem / (GY_*GZ_);

    for (int i = threadIdx.x; i < N_*C_*OP_; i += 128) {
        int j = i % OP_;
        int nc = i / OP_;                 // n*C_+c
        sW2[i] = pk2(W_N[(2*j)*(N_*C_) + nc], W_N[(2*j+1)*(N_*C_) + nc]);
    }
    for (int i = threadIdx.x; i < OC_*OP_; i += 128) {
        int j  = i % OP_;
        int oc = i / OP_;
        sWT2[i] = pk2(W_T[(2*j)*(T_*OC_) + t*OC_ + oc],
                      W_T[(2*j+1)*(T_*OC_) + t*OC_ + oc]);
    }
    if (threadIdx.x < OC_) sb[threadIdx.x] = b_N[threadIdx.x];
    if (threadIdx.x < N_) {
        const float* K = intr + b*9;
        const float* R = RT + ((size_t)((b*T_+t)*N_ + threadIdx.x))*16;
        #pragma unroll
        for (int i = 0; i < 3; i++)
            #pragma unroll
            for (int j = 0; j < 4; j++)
                sP[threadIdx.x*12 + i*4 + j] =
                    K[i*3+0]*R[0*4+j] + K[i*3+1]*R[1*4+j] + K[i*3+2]*R[2*4+j];
    }
    __syncthreads();

    float px = -50.0f + ((float)x  + 0.5f);
    float py = -50.0f + ((float)gy + 0.5f);
    float pz = -3.0f  + ((float)gz + 0.5f);

    u64 acc2[OP_];
    #pragma unroll
    for (int j = 0; j < OP_; j++) acc2[j] = pk2(sb[2*j], sb[2*j+1]);

    for (int n = 0; n < N_; n++) {
        const float* P = sP + n*12;
        float pr0 = P[0]*px + P[1]*py + P[2]*pz  + P[3];
        float pr1 = P[4]*px + P[5]*py + P[6]*pz  + P[7];
        float pr2 = P[8]*px + P[9]*py + P[10]*pz + P[11];
        float zc = fmaxf(pr2, 1e-5f);
        float u = pr0 / zc;
        float v = pr1 / zc;
        float d = (pr2 - 2.0f) / ((46.8f - 2.0f) / 48.0f);
        u = fminf(fmaxf(u, -1.0e6f), 1.0e6f);
        v = fminf(fmaxf(v, -1.0e6f), 1.0e6f);
        d = fminf(fmaxf(d, -1.0e6f), 1.0e6f);

        float fx0 = floorf(u), fy0 = floorf(v), fz0 = floorf(d);
        int x0 = (int)fx0, y0 = (int)fy0, z0 = (int)fz0;
        // fully outside -> zero contribution (GEMV of zeros) -> skip camera
        if (x0 < -1 || x0 > FW_-1 || y0 < -1 || y0 > FH_-1 ||
            z0 < -1 || z0 > FD_-1) continue;

        float wx1 = u - fx0, wy1 = v - fy0, wz1 = d - fz0;
        // masked weights (exact zeros for invalid sides) + clamped indices
        float wxm[2] = { (1.0f-wx1) * (float)(x0 >= 0), wx1 * (float)(x0 < FW_-1) };
        float wym[2] = { (1.0f-wy1) * (float)(y0 >= 0), wy1 * (float)(y0 < FH_-1) };
        float wzm[2] = { (1.0f-wz1) * (float)(z0 >= 0), wz1 * (float)(z0 < FD_-1) };
        int xc[2] = { max(x0, 0), min(x0+1, FW_-1) };
        int yc[2] = { max(y0, 0), min(y0+1, FH_-1) };
        int zcl[2] = { max(z0, 0), min(z0+1, FD_-1) };

        u64 s2[8];
        #pragma unroll
        for (int q = 0; q < 8; q++) s2[q] = 0ull;

        const __half* fb = g_featCL + (size_t)((b*T_+t)*N_ + n)*FEAT_PER_CAM;
        #pragma unroll
        for (int dz = 0; dz < 2; dz++) {
            #pragma unroll
            for (int dy = 0; dy < 2; dy++) {
                float wzy = wzm[dz]*wym[dy];
                int row = (zcl[dz]*FH_ + yc[dy])*FW_;
                #pragma unroll
                for (int dx = 0; dx < 2; dx++) {
                    float w = wzy*wxm[dx];
                    u64 ww = pk2(w, w);
                    union { uint4 u4; __half2 h[4]; } U0, U1;
                    const uint4* p = reinterpret_cast<const uint4*>(
                        fb + (size_t)(row + xc[dx])*C_);
                    U0.u4 = p[0]; U1.u4 = p[1];
                    #pragma unroll
                    for (int q = 0; q < 4; q++) {
                        float2 f0 = __half22float2(U0.h[q]);
                        s2[q]   = f2fma(pk2(f0.x, f0.y), ww, s2[q]);
                        float2 f1 = __half22float2(U1.h[q]);
                        s2[4+q] = f2fma(pk2(f1.x, f1.y), ww, s2[4+q]);
                    }
                }
            }
        }
        float s[C_];
        #pragma unroll
        for (int q = 0; q < 8; q++) upk2(s2[q], s[2*q], s[2*q+1]);

        // packed GEMV: acc2 += W_N[:, n*16+c] * s[c]   (LDS.128 weight loads)
        const ulonglong2* wp = reinterpret_cast<const ulonglong2*>(sW2 + n*C_*OP_);
        #pragma unroll
        for (int c = 0; c < C_; c++) {
            u64 bb = pk2(s[c], s[c]);
            #pragma unroll
            for (int q = 0; q < OP_/2; q++) {
                ulonglong2 wv = wp[c*(OP_/2) + q];
                acc2[2*q]   = f2fma(wv.x, bb, acc2[2*q]);
                acc2[2*q+1] = f2fma(wv.y, bb, acc2[2*q+1]);
            }
        }
    }

    // ReLU
    float h[OC_];
    #pragma unroll
    for (int j = 0; j < OP_; j++) {
        float lo, hi; upk2(acc2[j], lo, hi);
        h[2*j]   = fmaxf(lo, 0.0f);
        h[2*j+1] = fmaxf(hi, 0.0f);
    }

    // packed premultiply by this t's W_T slice (40x40), LDS.128 weights
    u64 out2[OP_];
    #pragma unroll
    for (int j = 0; j < OP_; j++) out2[j] = 0ull;
    const ulonglong2* wq = reinterpret_cast<const ulonglong2*>(sWT2);
    #pragma unroll
    for (int oc = 0; oc < OC_; oc++) {
        u64 bb = pk2(h[oc], h[oc]);
        #pragma unroll
        for (int q = 0; q < OP_/2; q++) {
            ulonglong2 wv = wq[oc*(OP_/2) + q];
            out2[2*q]   = f2fma(wv.x, bb, out2[2*q]);
            out2[2*q+1] = f2fma(wv.y, bb, out2[2*q+1]);
        }
    }

    // store fp16 h'
    union { uint4 q[5]; __half2 h2[OP_]; } O;
    #pragma unroll
    for (int j = 0; j < OP_; j++) {
        float lo, hi; upk2(out2[j], lo, hi);
        O.h2[j] = __floats2half2_rn(lo, hi);
    }
    uint4* dst = reinterpret_cast<uint4*>(g_h + (size_t)pos * OC_);
    #pragma unroll
    for (int q = 0; q < 5; q++) dst[q] = O.q[q];
}

// ---------------------------------------------------------------------------
// Kernel 2: per (b,dd,hh,wy): for each t, warp via cum matrix, trilinear-sample
// the 40 premultiplied fp16 channels of h', accumulate (+b_T), ReLU, write out.
// ---------------------------------------------------------------------------
__global__ void __launch_bounds__(128) k_warp(
    const float* __restrict__ b_T, float* __restrict__ out)
{
    __shared__ float sb[OC_];
    __shared__ float sC[T_*12];

    int pos = blockIdx.x*128 + threadIdx.x;     // 160000 total
    int b   = pos / VOXN;                       // block-uniform
    int rem = pos % VOXN;
    int wy  = rem % GY_;                        // Wp index
    int hh  = (rem / GY_) % GZ_;                // Hp index
    int dd  = rem / (GY_*GZ_);                  // Dp index

    if (threadIdx.x < OC_)    sb[threadIdx.x] = b_T[threadIdx.x];
    if (threadIdx.x < T_*12)  sC[threadIdx.x] = g_cum[b*T_*12 + threadIdx.x];
    __syncthreads();

    float bx = -1.0f + 2.0f*(float)wy / (float)(GY_-1);
    float by = -1.0f + 2.0f*(float)hh / (float)(GZ_-1);
    float bz = -1.0f + 2.0f*(float)dd / (float)(GX_-1);

    u64 acc2[OP_];
    #pragma unroll
    for (int j = 0; j < OP_; j++) acc2[j] = pk2(sb[2*j], sb[2*j+1]);

    for (int t = 0; t < T_; t++) {
        const float* th = sC + t*12;
        float gx = th[0]*bx + th[1]*by + th[2]*bz  + th[3];
        float gy = th[4]*bx + th[5]*by + th[6]*bz  + th[7];
        float gz = th[8]*bx + th[9]*by + th[10]*bz + th[11];
        float ix = (gx + 1.0f)*0.5f*(float)(GY_-1);   // Wp
        float iy = (gy + 1.0f)*0.5f*(float)(GZ_-1);   // Hp
        float iz = (gz + 1.0f)*0.5f*(float)(GX_-1);   // Dp
        ix = fminf(fmaxf(ix, -1.0e6f), 1.0e6f);
        iy = fminf(fmaxf(iy, -1.0e6f), 1.0e6f);
        iz = fminf(fmaxf(iz, -1.0e6f), 1.0e6f);

        float fx0 = floorf(ix), fy0 = floorf(iy), fz0 = floorf(iz);
        int x0 = (int)fx0, y0 = (int)fy0, z0 = (int)fz0;
        if (x0 < -1 || x0 > GY_-1 || y0 < -1 || y0 > GZ_-1 ||
            z0 < -1 || z0 > GX_-1) continue;

        float wx1 = ix - fx0, wy1 = iy - fy0, wz1 = iz - fz0;
        float wxm[2] = { (1.0f-wx1) * (float)(x0 >= 0), wx1 * (float)(x0 < GY_-1) };
        float wym[2] = { (1.0f-wy1) * (float)(y0 >= 0), wy1 * (float)(y0 < GZ_-1) };
        float wzm[2] = { (1.0f-wz1) * (float)(z0 >= 0), wz1 * (float)(z0 < GX_-1) };
        int xc[2]  = { max(x0, 0), min(x0+1, GY_-1) };
        int yc[2]  = { max(y0, 0), min(y0+1, GZ_-1) };
        int zcl[2] = { max(z0, 0), min(z0+1, GX_-1) };

        const __half* hb = g_h + (size_t)(b*T_+t)*VOXN*OC_;
        #pragma unroll
        for (int dz = 0; dz < 2; dz++) {
            #pragma unroll
            for (int dy = 0; dy < 2; dy++) {
                float wzy = wzm[dz]*wym[dy];
                int row = (zcl[dz]*GZ_ + yc[dy])*GY_;
                #pragma unroll
                for (int dx = 0; dx < 2; dx++) {
                    float w = wzy*wxm[dx];
                    u64 ww = pk2(w, w);
                    const uint4* p = reinterpret_cast<const uint4*>(
                        hb + (size_t)(row + xc[dx])*OC_);
                    #pragma unroll
                    for (int q = 0; q < 5; q++) {
                        union { uint4 u4; __half2 h[4]; } U;
                        U.u4 = p[q];
                        #pragma unroll
                        for (int k = 0; k < 4; k++) {
                            float2 f = __half22float2(U.h[k]);
                            acc2[q*4+k] = f2fma(pk2(f.x, f.y), ww, acc2[q*4+k]);
                        }
                    }
                }
            }
        }
    }

    // out[b][o][dd][hh][wy]
    #pragma unroll
    for (int j = 0; j < OP_; j++) {
        float lo, hi; upk2(acc2[j], lo, hi);
        out[(((size_t)(b*OC_ + 2*j  )*GX_ + dd)*GZ_ + hh)*GY_ + wy] = fmaxf(lo, 0.0f);
        out[(((size_t)(b*OC_ + 2*j+1)*GX_ + dd)*GZ_ + hh)*GY_ + wy] = fmaxf(hi, 0.0f);
    }
}

// ---------------------------------------------------------------------------
extern "C" void kernel_launch(void* const* d_in, const int* in_sizes, int n_in,
                              void* d_out, int out_size) {
    const float* frustum = (const float*)d_in[0];
    const float* RT      = (const float*)d_in[1];
    const float* intrins = (const float*)d_in[2];
    const float* DoF     = (const float*)d_in[3];
    const float* W_N     = (const float*)d_in[4];
    const float* b_N     = (const float*)d_in[5];
    const float* W_T     = (const float*)d_in[6];
    const float* b_T     = (const float*)d_in[7];
    float* out = (float*)d_out;

    k_transpose<<<B_*T_*N_*FD_*FH_, 256>>>(frustum);
    k_cum<<<1, 32>>>(DoF);
    k_frustum<<<(B_*T_*VOXN)/128, 128>>>(RT, intrins, W_N, b_N, W_T);
    k_warp<<<(B_*VOXN)/128, 128>>>(b_T, out);
}

// round 13
// speedup vs baseline: 1.8228x; 1.0001x over previous
#include <cuda_runtime.h>
#include <cuda_bf16.h>
#include <cuda_fp16.h>
#include <math.h>

#define B_  2
#define T_  3
#define N_  6
#define C_  16
#define FD_ 48
#define FH_ 24
#define FW_ 64
#define GX_ 100
#define GY_ 100
#define GZ_ 8
#define OC_ 40
#define OP_ (OC_/2)                  // 20 output pairs

#define VOXN (GX_*GZ_*GY_)           // 80000 spatial positions per (b,t)
#define FEAT_PER_CAM (FD_*FH_*FW_*C_)

typedef unsigned long long u64;

// ---- packed-f32x2 helpers (FFMA2 — only reachable via PTX) --------------
__device__ __forceinline__ u64 pk2(float lo, float hi) {
    u64 r; asm("mov.b64 %0, {%1, %2};" : "=l"(r) : "f"(lo), "f"(hi)); return r;
}
__device__ __forceinline__ void upk2(u64 v, float& lo, float& hi) {
    asm("mov.b64 {%0, %1}, %2;" : "=f"(lo), "=f"(hi) : "l"(v));
}
__device__ __forceinline__ u64 f2fma(u64 a, u64 b, u64 c) {
    u64 d; asm("fma.rn.f32x2 %0, %1, %2, %3;" : "=l"(d) : "l"(a), "l"(b), "l"(c)); return d;
}

// Scratch (static device allocations — no cudaMalloc allowed)
__device__ __half g_featCL[(size_t)B_*T_*N_*FD_*FH_*FW_*C_]; // channel-last fp16 (~85MB)
__device__ __half g_h[(size_t)B_*T_*VOXN*OC_];               // W_T-premultiplied h', fp16 channel-last (~38MB)
__device__ float  g_cum[B_*T_*12];                           // top-3 rows of cumulative warp matrices

// ---------------------------------------------------------------------------
// Kernel 0: transpose frustum features [m][c][fd][fh][fw] -> [m][fd][fh][fw][c]
// fp32 in, fp16 out. One block per (m, fd, fh) row.
// ---------------------------------------------------------------------------
__global__ void k_transpose(const float* __restrict__ in) {
    __shared__ float tile[FW_*17];   // [fw][c], pad to kill bank conflicts
    int r  = blockIdx.x;                 // over B*T*N*FD*FH
    int m  = r / (FD_*FH_);
    int dh = r % (FD_*FH_);
    for (int idx = threadIdx.x; idx < C_*FW_; idx += blockDim.x) {
        int c  = idx / FW_;
        int fw = idx % FW_;
        tile[fw*17 + c] = in[(((size_t)m*C_ + c)*(FD_*FH_) + dh)*FW_ + fw];
    }
    __syncthreads();
    __half2* dst = reinterpret_cast<__half2*>(g_featCL + (size_t)r * (FW_*C_));
    for (int j = threadIdx.x; j < C_*FW_/2; j += blockDim.x) {
        int fw = j / (C_/2);
        int c  = (j % (C_/2)) * 2;
        dst[j] = __floats2half2_rn(tile[fw*17 + c], tile[fw*17 + c + 1]);
    }
}

// ---------------------------------------------------------------------------
// Cumulative warp matrices.  cum_{T-1}=I; cum_t = M4[t] @ cum_{t+1}
// ---------------------------------------------------------------------------
__global__ void k_cum(const float* __restrict__ DoF) {
    int b = threadIdx.x;
    if (b >= B_) return;
    float cum[16] = {1,0,0,0, 0,1,0,0, 0,0,1,0, 0,0,0,1};
    for (int t = T_-1; t >= 0; --t) {
        if (t < T_-1) {
            float M[16];
            #pragma unroll
            for (int i = 0; i < 3; i++)
                #pragma unroll
                for (int j = 0; j < 4; j++)
                    M[i*4+j] = DoF[((b*T_ + t)*4 + i)*4 + j];
            M[12]=0.f; M[13]=0.f; M[14]=0.f; M[15]=1.f;
            float nc[16];
            #pragma unroll
            for (int i = 0; i < 4; i++)
                #pragma unroll
                for (int j = 0; j < 4; j++) {
                    float a = 0.f;
                    #pragma unroll
                    for (int k = 0; k < 4; k++) a += M[i*4+k]*cum[k*4+j];
                    nc[i*4+j] = a;
                }
            #pragma unroll
            for (int i = 0; i < 16; i++) cum[i] = nc[i];
        }
        for (int i = 0; i < 12; i++) g_cum[(b*T_+t)*12 + i] = cum[i];
    }
}

// ---------------------------------------------------------------------------
// Kernel 1: per voxel (b,t,x,gz,gy): project into 6 cams, trilinear-sample 16
// fp16 channels, W_N (96->40) + b_N + ReLU, premultiply by per-t W_T slice,
// store h' channel-last fp16.  GEMVs on fma.rn.f32x2 with LDS.128 weight
// loads; trilinear accumulate also packed; branchless corner masking.
// ---------------------------------------------------------------------------
__global__ void __launch_bounds__(128) k_frustum(
    const float* __restrict__ RT, const float* __restrict__ intr,
    const float* __restrict__ W_N, const float* __restrict__ b_N,
    const float* __restrict__ W_T)
{
    __shared__ float sP[N_*12];                       // fused K @ RT[:3,:]
    __shared__ __align__(16) u64 sW2[N_*C_*OP_];      // W_N packed [n][c][j]
    __shared__ __align__(16) u64 sWT2[OC_*OP_];       // per-t W_T slice [oc][j]
    __shared__ float sb[OC_];

    int pos = blockIdx.x*128 + threadIdx.x;     // 480000 total; VOXN%128==0
    int bt  = pos / VOXN;                       // block-uniform
    int t   = bt % T_;
    int b   = bt / T_;
    int rem = pos % VOXN;
    int gy  = rem % GY_;
    int gz  = (rem / GY_) % GZ_;
    int x   = rem / (GY_*GZ_);

    for (int i = threadIdx.x; i < N_*C_*OP_; i += 128) {
        int j = i % OP_;
        int nc = i / OP_;                 // n*C_+c
        sW2[i] = pk2(W_N[(2*j)*(N_*C_) + nc], W_N[(2*j+1)*(N_*C_) + nc]);
    }
    for (int i = threadIdx.x; i < OC_*OP_; i += 128) {
        int j  = i % OP_;
        int oc = i / OP_;
        sWT2[i] = pk2(W_T[(2*j)*(T_*OC_) + t*OC_ + oc],
                      W_T[(2*j+1)*(T_*OC_) + t*OC_ + oc]);
    }
    if (threadIdx.x < OC_) sb[threadIdx.x] = b_N[threadIdx.x];
    if (threadIdx.x < N_) {
        const float* K = intr + b*9;
        const float* R = RT + ((size_t)((b*T_+t)*N_ + threadIdx.x))*16;
        #pragma unroll
        for (int i = 0; i < 3; i++)
            #pragma unroll
            for (int j = 0; j < 4; j++)
                sP[threadIdx.x*12 + i*4 + j] =
                    K[i*3+0]*R[0*4+j] + K[i*3+1]*R[1*4+j] + K[i*3+2]*R[2*4+j];
    }
    __syncthreads();

    float px = -50.0f + ((float)x  + 0.5f);
    float py = -50.0f + ((float)gy + 0.5f);
    float pz = -3.0f  + ((float)gz + 0.5f);

    u64 acc2[OP_];
    #pragma unroll
    for (int j = 0; j < OP_; j++) acc2[j] = pk2(sb[2*j], sb[2*j+1]);

    for (int n = 0; n < N_; n++) {
        const float* P = sP + n*12;
        float pr0 = P[0]*px + P[1]*py + P[2]*pz  + P[3];
        float pr1 = P[4]*px + P[5]*py + P[6]*pz  + P[7];
        float pr2 = P[8]*px + P[9]*py + P[10]*pz + P[11];
        float zc = fmaxf(pr2, 1e-5f);
        float u = pr0 / zc;
        float v = pr1 / zc;
        float d = (pr2 - 2.0f) / ((46.8f - 2.0f) / 48.0f);
        u = fminf(fmaxf(u, -1.0e6f), 1.0e6f);
        v = fminf(fmaxf(v, -1.0e6f), 1.0e6f);
        d = fminf(fmaxf(d, -1.0e6f), 1.0e6f);

        float fx0 = floorf(u), fy0 = floorf(v), fz0 = floorf(d);
        int x0 = (int)fx0, y0 = (int)fy0, z0 = (int)fz0;
        // fully outside -> zero contribution (GEMV of zeros) -> skip camera
        if (x0 < -1 || x0 > FW_-1 || y0 < -1 || y0 > FH_-1 ||
            z0 < -1 || z0 > FD_-1) continue;

        float wx1 = u - fx0, wy1 = v - fy0, wz1 = d - fz0;
        // masked weights (exact zeros for invalid sides) + clamped indices
        float wxm[2] = { (1.0f-wx1) * (float)(x0 >= 0), wx1 * (float)(x0 < FW_-1) };
        float wym[2] = { (1.0f-wy1) * (float)(y0 >= 0), wy1 * (float)(y0 < FH_-1) };
        float wzm[2] = { (1.0f-wz1) * (float)(z0 >= 0), wz1 * (float)(z0 < FD_-1) };
        int xc[2] = { max(x0, 0), min(x0+1, FW_-1) };
        int yc[2] = { max(y0, 0), min(y0+1, FH_-1) };
        int zcl[2] = { max(z0, 0), min(z0+1, FD_-1) };

        u64 s2[8];
        #pragma unroll
        for (int q = 0; q < 8; q++) s2[q] = 0ull;

        const __half* fb = g_featCL + (size_t)((b*T_+t)*N_ + n)*FEAT_PER_CAM;
        #pragma unroll
        for (int dz = 0; dz < 2; dz++) {
            #pragma unroll
            for (int dy = 0; dy < 2; dy++) {
                float wzy = wzm[dz]*wym[dy];
                int row = (zcl[dz]*FH_ + yc[dy])*FW_;
                #pragma unroll
                for (int dx = 0; dx < 2; dx++) {
                    float w = wzy*wxm[dx];
                    u64 ww = pk2(w, w);
                    union { uint4 u4; __half2 h[4]; } U0, U1;
                    const uint4* p = reinterpret_cast<const uint4*>(
                        fb + (size_t)(row + xc[dx])*C_);
                    U0.u4 = p[0]; U1.u4 = p[1];
                    #pragma unroll
                    for (int q = 0; q < 4; q++) {
                        float2 f0 = __half22float2(U0.h[q]);
                        s2[q]   = f2fma(pk2(f0.x, f0.y), ww, s2[q]);
                        float2 f1 = __half22float2(U1.h[q]);
                        s2[4+q] = f2fma(pk2(f1.x, f1.y), ww, s2[4+q]);
                    }
                }
            }
        }
        float s[C_];
        #pragma unroll
        for (int q = 0; q < 8; q++) upk2(s2[q], s[2*q], s[2*q+1]);

        // packed GEMV: acc2 += W_N[:, n*16+c] * s[c]   (LDS.128 weight loads)
        const ulonglong2* wp = reinterpret_cast<const ulonglong2*>(sW2 + n*C_*OP_);
        #pragma unroll
        for (int c = 0; c < C_; c++) {
            u64 bb = pk2(s[c], s[c]);
            #pragma unroll
            for (int q = 0; q < OP_/2; q++) {
                ulonglong2 wv = wp[c*(OP_/2) + q];
                acc2[2*q]   = f2fma(wv.x, bb, acc2[2*q]);
                acc2[2*q+1] = f2fma(wv.y, bb, acc2[2*q+1]);
            }
        }
    }

    // ReLU
    float h[OC_];
    #pragma unroll
    for (int j = 0; j < OP_; j++) {
        float lo, hi; upk2(acc2[j], lo, hi);
        h[2*j]   = fmaxf(lo, 0.0f);
        h[2*j+1] = fmaxf(hi, 0.0f);
    }

    // packed premultiply by this t's W_T slice (40x40), LDS.128 weights
    u64 out2[OP_];
    #pragma unroll
    for (int j = 0; j < OP_; j++) out2[j] = 0ull;
    const ulonglong2* wq = reinterpret_cast<const ulonglong2*>(sWT2);
    #pragma unroll
    for (int oc = 0; oc < OC_; oc++) {
        u64 bb = pk2(h[oc], h[oc]);
        #pragma unroll
        for (int q = 0; q < OP_/2; q++) {
            ulonglong2 wv = wq[oc*(OP_/2) + q];
            out2[2*q]   = f2fma(wv.x, bb, out2[2*q]);
            out2[2*q+1] = f2fma(wv.y, bb, out2[2*q+1]);
        }
    }

    // store fp16 h'
    union { uint4 q[5]; __half2 h2[OP_]; } O;
    #pragma unroll
    for (int j = 0; j < OP_; j++) {
        float lo, hi; upk2(out2[j], lo, hi);
        O.h2[j] = __floats2half2_rn(lo, hi);
    }
    uint4* dst = reinterpret_cast<uint4*>(g_h + (size_t)pos * OC_);
    #pragma unroll
    for (int q = 0; q < 5; q++) dst[q] = O.q[q];
}

// ---------------------------------------------------------------------------
// Kernel 2: per (b,dd,hh,wy): for each t, warp via cum matrix, trilinear-sample
// the 40 premultiplied fp16 channels of h', accumulate (+b_T), ReLU, write out.
// ---------------------------------------------------------------------------
__global__ void __launch_bounds__(128) k_warp(
    const float* __restrict__ b_T, float* __restrict__ out)
{
    __shared__ float sb[OC_];
    __shared__ float sC[T_*12];

    int pos = blockIdx.x*128 + threadIdx.x;     // 160000 total
    int b   = pos / VOXN;                       // block-uniform
    int rem = pos % VOXN;
    int wy  = rem % GY_;                        // Wp index
    int hh  = (rem / GY_) % GZ_;                // Hp index
    int dd  = rem / (GY_*GZ_);                  // Dp index

    if (threadIdx.x < OC_)    sb[threadIdx.x] = b_T[threadIdx.x];
    if (threadIdx.x < T_*12)  sC[threadIdx.x] = g_cum[b*T_*12 + threadIdx.x];
    __syncthreads();

    float bx = -1.0f + 2.0f*(float)wy / (float)(GY_-1);
    float by = -1.0f + 2.0f*(float)hh / (float)(GZ_-1);
    float bz = -1.0f + 2.0f*(float)dd / (float)(GX_-1);

    u64 acc2[OP_];
    #pragma unroll
    for (int j = 0; j < OP_; j++) acc2[j] = pk2(sb[2*j], sb[2*j+1]);

    for (int t = 0; t < T_; t++) {
        const float* th = sC + t*12;
        float gx = th[0]*bx + th[1]*by + th[2]*bz  + th[3];
        float gy = th[4]*bx + th[5]*by + th[6]*bz  + th[7];
        float gz = th[8]*bx + th[9]*by + th[10]*bz + th[11];
        float ix = (gx + 1.0f)*0.5f*(float)(GY_-1);   // Wp
        float iy = (gy + 1.0f)*0.5f*(float)(GZ_-1);   // Hp
        float iz = (gz + 1.0f)*0.5f*(float)(GX_-1);   // Dp
        ix = fminf(fmaxf(ix, -1.0e6f), 1.0e6f);
        iy = fminf(fmaxf(iy, -1.0e6f), 1.0e6f);
        iz = fminf(fmaxf(iz, -1.0e6f), 1.0e6f);

        float fx0 = floorf(ix), fy0 = floorf(iy), fz0 = floorf(iz);
        int x0 = (int)fx0, y0 = (int)fy0, z0 = (int)fz0;
        if (x0 < -1 || x0 > GY_-1 || y0 < -1 || y0 > GZ_-1 ||
            z0 < -1 || z0 > GX_-1) continue;

        float wx1 = ix - fx0, wy1 = iy - fy0, wz1 = iz - fz0;
        float wxm[2] = { (1.0f-wx1) * (float)(x0 >= 0), wx1 * (float)(x0 < GY_-1) };
        float wym[2] = { (1.0f-wy1) * (float)(y0 >= 0), wy1 * (float)(y0 < GZ_-1) };
        float wzm[2] = { (1.0f-wz1) * (float)(z0 >= 0), wz1 * (float)(z0 < GX_-1) };
        int xc[2]  = { max(x0, 0), min(x0+1, GY_-1) };
        int yc[2]  = { max(y0, 0), min(y0+1, GZ_-1) };
        int zcl[2] = { max(z0, 0), min(z0+1, GX_-1) };

        const __half* hb = g_h + (size_t)(b*T_+t)*VOXN*OC_;
        #pragma unroll
        for (int dz = 0; dz < 2; dz++) {
            #pragma unroll
            for (int dy = 0; dy < 2; dy++) {
                float wzy = wzm[dz]*wym[dy];
                int row = (zcl[dz]*GZ_ + yc[dy])*GY_;
                #pragma unroll
                for (int dx = 0; dx < 2; dx++) {
                    float w = wzy*wxm[dx];
                    u64 ww = pk2(w, w);
                    const uint4* p = reinterpret_cast<const uint4*>(
                        hb + (size_t)(row + xc[dx])*OC_);
                    #pragma unroll
                    for (int q = 0; q < 5; q++) {
                        union { uint4 u4; __half2 h[4]; } U;
                        U.u4 = p[q];
                        #pragma unroll
                        for (int k = 0; k < 4; k++) {
                            float2 f = __half22float2(U.h[k]);
                            acc2[q*4+k] = f2fma(pk2(f.x, f.y), ww, acc2[q*4+k]);
                        }
                    }
                }
            }
        }
    }

    // out[b][o][dd][hh][wy]
    #pragma unroll
    for (int j = 0; j < OP_; j++) {
        float lo, hi; upk2(acc2[j], lo, hi);
        out[(((size_t)(b*OC_ + 2*j  )*GX_ + dd)*GZ_ + hh)*GY_ + wy] = fmaxf(lo, 0.0f);
        out[(((size_t)(b*OC_ + 2*j+1)*GX_ + dd)*GZ_ + hh)*GY_ + wy] = fmaxf(hi, 0.0f);
    }
}

// ---------------------------------------------------------------------------
extern "C" void kernel_launch(void* const* d_in, const int* in_sizes, int n_in,
                              void* d_out, int out_size) {
    const float* frustum = (const float*)d_in[0];
    const float* RT      = (const float*)d_in[1];
    const float* intrins = (const float*)d_in[2];
    const float* DoF     = (const float*)d_in[3];
    const float* W_N     = (const float*)d_in[4];
    const float* b_N     = (const float*)d_in[5];
    const float* W_T     = (const float*)d_in[6];
    const float* b_T     = (const float*)d_in[7];
    float* out = (float*)d_out;

    k_transpose<<<B_*T_*N_*FD_*FH_, 256>>>(frustum);
    k_cum<<<1, 32>>>(DoF);
    k_frustum<<<(B_*T_*VOXN)/128, 128>>>(RT, intrins, W_N, b_N, W_T);
    k_warp<<<(B_*VOXN)/128, 128>>>(b_T, out);
}